// round 1
// baseline (speedup 1.0000x reference)
#include <cuda_runtime.h>
#include <cuda_bf16.h>
#include <float.h>
#include <stdint.h>

// ---------------------------------------------------------------------------
// Problem constants (fixed shapes for SparseVLMModel_59725815218738)
// ---------------------------------------------------------------------------
#define B_SZ    64
#define S_SZ    197
#define P_SZ    196      // patch tokens (skip CLS)
#define T_SZ    512
#define DV      768
#define DL      4096
#define TOPK    32
#define OUT_S   (TOPK + T_SZ)   // 544
#define LN_EPS  1e-5

// Scratch (no cudaMalloc allowed)
__device__ float g_scores[B_SZ * P_SZ];
__device__ int   g_topk[B_SZ * TOPK];
__device__ int   g_is64;

typedef unsigned long long u64;

__device__ __forceinline__ u64 pack2(float lo, float hi) {
    u64 r; asm("mov.b64 %0, {%1, %2};" : "=l"(r) : "f"(lo), "f"(hi)); return r;
}
__device__ __forceinline__ void ffma2(u64& c, u64 a, u64 b) {
    asm("fma.rn.f32x2 %0, %1, %2, %0;" : "+l"(c) : "l"(a), "l"(b));
}
__device__ __forceinline__ float2 unpack2(u64 v) {
    float2 f; asm("mov.b64 {%0, %1}, %2;" : "=f"(f.x), "=f"(f.y) : "l"(v)); return f;
}

// ---------------------------------------------------------------------------
// 0. Sniff int32 vs int64 ids. ids < 32000, so int64 => every odd word == 0.
// ---------------------------------------------------------------------------
__global__ void sniff_kernel(const int* __restrict__ ids) {
    unsigned nz = __ballot_sync(0xffffffffu, ids[2 * threadIdx.x + 1] != 0);
    if (threadIdx.x == 0) g_is64 = (nz == 0u) ? 1 : 0;
}

// ---------------------------------------------------------------------------
// 1. Per-row LayerNorm score (ordering-equivalent: constant shifts dropped).
//    score_rank = rstd * (sum(x*g*w) - mean * sum(g*w))
// ---------------------------------------------------------------------------
__global__ void scores_kernel(const float* __restrict__ vt,
                              const float* __restrict__ gamma,
                              const float* __restrict__ beta,
                              const float* __restrict__ w) {
    int row = blockIdx.x;                 // 0..12543
    int b = row / P_SZ, s = row % P_SZ;
    const float* x = vt + (size_t)(b * S_SZ + 1 + s) * DV;
    int tid = threadIdx.x;                // 128 threads

    double s1 = 0.0, s2 = 0.0, sgw = 0.0, cgw = 0.0;
    #pragma unroll
    for (int i = tid; i < DV; i += 128) {
        double xv = (double)x[i];
        double gw = (double)gamma[i] * (double)w[i];
        s1 += xv; s2 += xv * xv; sgw += xv * gw; cgw += gw;
    }

    __shared__ double sh[4][128];
    sh[0][tid] = s1; sh[1][tid] = s2; sh[2][tid] = sgw; sh[3][tid] = cgw;
    __syncthreads();
    for (int st = 64; st > 0; st >>= 1) {
        if (tid < st) {
            sh[0][tid] += sh[0][tid + st];
            sh[1][tid] += sh[1][tid + st];
            sh[2][tid] += sh[2][tid + st];
            sh[3][tid] += sh[3][tid + st];
        }
        __syncthreads();
    }
    if (tid == 0) {
        double mean = sh[0][0] / (double)DV;
        double var  = sh[1][0] / (double)DV - mean * mean;
        double rstd = rsqrt(var + LN_EPS);
        g_scores[row] = (float)(rstd * (sh[2][0] - mean * sh[3][0]));
    }
}

// ---------------------------------------------------------------------------
// 2. Top-32 per batch, descending, stable (lower index wins ties) = lax.top_k
// ---------------------------------------------------------------------------
__global__ void topk_kernel() {
    __shared__ float sc[256];
    __shared__ float rv[256];
    __shared__ int   ri[256];
    int b = blockIdx.x, t = threadIdx.x;
    sc[t] = (t < P_SZ) ? g_scores[b * P_SZ + t] : -FLT_MAX;
    __syncthreads();
    for (int k = 0; k < TOPK; k++) {
        rv[t] = sc[t]; ri[t] = t;
        __syncthreads();
        for (int st = 128; st > 0; st >>= 1) {
            if (t < st) {
                float v2 = rv[t + st]; int i2 = ri[t + st];
                if (v2 > rv[t] || (v2 == rv[t] && i2 < ri[t])) { rv[t] = v2; ri[t] = i2; }
            }
            __syncthreads();
        }
        if (t == 0) {
            g_topk[b * TOPK + k] = ri[0];
            sc[ri[0]] = -FLT_MAX;
        }
        __syncthreads();
    }
}

// ---------------------------------------------------------------------------
// 3. Visual GEMM: out[b*544+k, :] = gather(vt)[b,k,:768] @ W[768,4096] + bias
//    64x64 tile / block, 256 threads, 4x4 per thread, FFMA2 (f32x2) inner.
// ---------------------------------------------------------------------------
#define GBM 64
#define GBN 64
#define GBK 32
__global__ void __launch_bounds__(256, 4)
gemm_kernel(const float* __restrict__ vt,
            const float* __restrict__ W,
            const float* __restrict__ bias,
            float* __restrict__ out) {
    __shared__ float As[GBK][GBM];   // transposed A tile
    __shared__ float Bs[GBK][GBN];
    __shared__ int   arow[GBM];

    int tid = threadIdx.x;           // 256
    int m0 = blockIdx.y * GBM;
    int n0 = blockIdx.x * GBN;

    if (tid < GBM) {
        int m = m0 + tid;
        int b = m >> 5;              // /32
        int idx = g_topk[m];
        arow[tid] = (b * S_SZ + 1 + idx) * DV;
    }
    __syncthreads();

    int ty = tid >> 4, tx = tid & 15;      // 16x16 threads -> 4x4 outputs each
    u64 acc[4][2];
    #pragma unroll
    for (int i = 0; i < 4; i++) { acc[i][0] = 0ull; acc[i][1] = 0ull; }

    float4 bias4 = *(const float4*)(bias + n0 + tx * 4);

    for (int kt = 0; kt < DV; kt += GBK) {
        // A tile: 64 rows x 32 k, gathered. 512 float4, 2 per thread.
        #pragma unroll
        for (int i = 0; i < 2; i++) {
            int f = tid + i * 256;
            int row = f >> 3, kc = (f & 7) * 4;
            float4 v = *(const float4*)(vt + arow[row] + kt + kc);
            As[kc + 0][row] = v.x; As[kc + 1][row] = v.y;
            As[kc + 2][row] = v.z; As[kc + 3][row] = v.w;
        }
        // B tile: 32 k x 64 n. 512 float4, 2 per thread.
        #pragma unroll
        for (int i = 0; i < 2; i++) {
            int f = tid + i * 256;
            int kr = f >> 4, nc = (f & 15) * 4;
            *(float4*)&Bs[kr][nc] = *(const float4*)(W + (size_t)(kt + kr) * DL + n0 + nc);
        }
        __syncthreads();

        #pragma unroll
        for (int k = 0; k < GBK; k++) {
            float4 a = *(const float4*)&As[k][ty * 4];
            float4 bv = *(const float4*)&Bs[k][tx * 4];
            u64 b01 = pack2(bv.x, bv.y);
            u64 b23 = pack2(bv.z, bv.w);
            u64 a0 = pack2(a.x, a.x);
            u64 a1 = pack2(a.y, a.y);
            u64 a2 = pack2(a.z, a.z);
            u64 a3 = pack2(a.w, a.w);
            ffma2(acc[0][0], a0, b01); ffma2(acc[0][1], a0, b23);
            ffma2(acc[1][0], a1, b01); ffma2(acc[1][1], a1, b23);
            ffma2(acc[2][0], a2, b01); ffma2(acc[2][1], a2, b23);
            ffma2(acc[3][0], a3, b01); ffma2(acc[3][1], a3, b23);
        }
        __syncthreads();
    }

    #pragma unroll
    for (int i = 0; i < 4; i++) {
        int m = m0 + ty * 4 + i;
        int b = m >> 5, kk = m & 31;
        float2 c0 = unpack2(acc[i][0]);
        float2 c1 = unpack2(acc[i][1]);
        float4 r;
        r.x = c0.x + bias4.x; r.y = c0.y + bias4.y;
        r.z = c1.x + bias4.z; r.w = c1.y + bias4.w;
        *(float4*)(out + (size_t)(b * OUT_S + kk) * DL + n0 + tx * 4) = r;
    }
}

// ---------------------------------------------------------------------------
// 4. Embedding gather into concat region: out[b, 32+t, :] = table[id]
// ---------------------------------------------------------------------------
__global__ void gather_kernel(const void* __restrict__ ids_raw,
                              const float* __restrict__ table,
                              float* __restrict__ out) {
    int r = blockIdx.x;               // 0..32767
    int b = r >> 9, t = r & 511;
    long long id;
    if (g_is64) id = ((const long long*)ids_raw)[r];
    else        id = (long long)((const int*)ids_raw)[r];

    const float4* src = (const float4*)(table + (size_t)id * DL);
    float4* dst = (float4*)(out + (size_t)(b * OUT_S + TOPK + t) * DL);
    int tid = threadIdx.x;            // 256 threads x 4 float4 = 4096 floats
    #pragma unroll
    for (int i = 0; i < 4; i++) dst[tid + i * 256] = src[tid + i * 256];
}

// ---------------------------------------------------------------------------
// kernel_launch
// metadata order: vision_tokens, input_ids, ln_gamma, ln_beta, scorer_w,
//                 scorer_b, proj_w, proj_b, embed_table
// ---------------------------------------------------------------------------
extern "C" void kernel_launch(void* const* d_in, const int* in_sizes, int n_in,
                              void* d_out, int out_size) {
    const float* vision_tokens = (const float*)d_in[0];
    const void*  input_ids     = d_in[1];
    const float* ln_gamma      = (const float*)d_in[2];
    const float* ln_beta       = (const float*)d_in[3];
    const float* scorer_w      = (const float*)d_in[4];
    // d_in[5] scorer_b: constant shift, irrelevant to top-k ordering
    const float* proj_w        = (const float*)d_in[6];
    const float* proj_b        = (const float*)d_in[7];
    const float* embed_table   = (const float*)d_in[8];
    float* out = (float*)d_out;

    sniff_kernel<<<1, 32>>>((const int*)input_ids);
    scores_kernel<<<B_SZ * P_SZ, 128>>>(vision_tokens, ln_gamma, ln_beta, scorer_w);
    topk_kernel<<<B_SZ, 256>>>();
    {
        dim3 grid(DL / GBN, (B_SZ * TOPK) / GBM);   // 64 x 32
        gemm_kernel<<<grid, 256>>>(vision_tokens, proj_w, proj_b, out);
    }
    gather_kernel<<<B_SZ * T_SZ, 256>>>(input_ids, embed_table, out);
}

// round 2
// speedup vs baseline: 1.1231x; 1.1231x over previous
#include <cuda_runtime.h>
#include <cuda_bf16.h>
#include <float.h>
#include <stdint.h>

// ---------------------------------------------------------------------------
// Problem constants (fixed shapes for SparseVLMModel_59725815218738)
// ---------------------------------------------------------------------------
#define B_SZ    64
#define S_SZ    197
#define P_SZ    196      // patch tokens (skip CLS)
#define T_SZ    512
#define DV      768
#define DL      4096
#define TOPK    32
#define OUT_S   (TOPK + T_SZ)   // 544
#define LN_EPS  1e-5

// Scratch (no cudaMalloc allowed)
__device__ float g_scores[B_SZ * P_SZ];
__device__ int   g_topk[B_SZ * TOPK];
__device__ int   g_is64;

typedef unsigned long long u64;

__device__ __forceinline__ u64 pack2(float lo, float hi) {
    u64 r; asm("mov.b64 %0, {%1, %2};" : "=l"(r) : "f"(lo), "f"(hi)); return r;
}
__device__ __forceinline__ void ffma2(u64& c, u64 a, u64 b) {
    asm("fma.rn.f32x2 %0, %1, %2, %0;" : "+l"(c) : "l"(a), "l"(b));
}
__device__ __forceinline__ float2 unpack2(u64 v) {
    float2 f; asm("mov.b64 {%0, %1}, %2;" : "=f"(f.x), "=f"(f.y) : "l"(v)); return f;
}

// ---------------------------------------------------------------------------
// 0. Sniff int32 vs int64 ids. ids < 32000, so int64 => every odd word == 0.
// ---------------------------------------------------------------------------
__global__ void sniff_kernel(const int* __restrict__ ids) {
    unsigned nz = __ballot_sync(0xffffffffu, ids[2 * threadIdx.x + 1] != 0);
    if (threadIdx.x == 0) g_is64 = (nz == 0u) ? 1 : 0;
}

// ---------------------------------------------------------------------------
// 1. Per-row LayerNorm score (ordering-equivalent: constant shifts dropped).
//    score_rank = rstd * (sum(x*g*w) - mean * sum(g*w))
// ---------------------------------------------------------------------------
__global__ void scores_kernel(const float* __restrict__ vt,
                              const float* __restrict__ gamma,
                              const float* __restrict__ beta,
                              const float* __restrict__ w) {
    int row = blockIdx.x;                 // 0..12543
    int b = row / P_SZ, s = row % P_SZ;
    const float* x = vt + (size_t)(b * S_SZ + 1 + s) * DV;
    int tid = threadIdx.x;                // 128 threads

    double s1 = 0.0, s2 = 0.0, sgw = 0.0, cgw = 0.0;
    #pragma unroll
    for (int i = tid; i < DV; i += 128) {
        double xv = (double)x[i];
        double gw = (double)gamma[i] * (double)w[i];
        s1 += xv; s2 += xv * xv; sgw += xv * gw; cgw += gw;
    }

    __shared__ double sh[4][128];
    sh[0][tid] = s1; sh[1][tid] = s2; sh[2][tid] = sgw; sh[3][tid] = cgw;
    __syncthreads();
    for (int st = 64; st > 0; st >>= 1) {
        if (tid < st) {
            sh[0][tid] += sh[0][tid + st];
            sh[1][tid] += sh[1][tid + st];
            sh[2][tid] += sh[2][tid + st];
            sh[3][tid] += sh[3][tid + st];
        }
        __syncthreads();
    }
    if (tid == 0) {
        double mean = sh[0][0] / (double)DV;
        double var  = sh[1][0] / (double)DV - mean * mean;
        double rstd = rsqrt(var + LN_EPS);
        g_scores[row] = (float)(rstd * (sh[2][0] - mean * sh[3][0]));
    }
}

// ---------------------------------------------------------------------------
// 2. Top-32 per batch, descending, stable (lower index wins ties) = lax.top_k
// ---------------------------------------------------------------------------
__global__ void topk_kernel() {
    __shared__ float sc[256];
    __shared__ float rv[256];
    __shared__ int   ri[256];
    int b = blockIdx.x, t = threadIdx.x;
    sc[t] = (t < P_SZ) ? g_scores[b * P_SZ + t] : -FLT_MAX;
    __syncthreads();
    for (int k = 0; k < TOPK; k++) {
        rv[t] = sc[t]; ri[t] = t;
        __syncthreads();
        for (int st = 128; st > 0; st >>= 1) {
            if (t < st) {
                float v2 = rv[t + st]; int i2 = ri[t + st];
                if (v2 > rv[t] || (v2 == rv[t] && i2 < ri[t])) { rv[t] = v2; ri[t] = i2; }
            }
            __syncthreads();
        }
        if (t == 0) {
            g_topk[b * TOPK + k] = ri[0];
            sc[ri[0]] = -FLT_MAX;
        }
        __syncthreads();
    }
}

// ---------------------------------------------------------------------------
// 3. Fused kernel: blocks [0, NGEMM) do the visual-projection GEMM
//    (128x128x16 tiles, 8x8 per thread, FFMA2 inner loop);
//    blocks [NGEMM, NGEMM + 32768) do the embedding gather.
//    GEMM is FMA-bound, gather is DRAM-bound -> they overlap on
//    different pipes within one launch (graph-safe, no streams).
// ---------------------------------------------------------------------------
#define GBM 128
#define GBN 128
#define GBK 16
#define NGEMM ((B_SZ * TOPK / GBM) * (DL / GBN))   // 16 * 32 = 512
#define NGATHER (B_SZ * T_SZ)                       // 32768

__global__ void __launch_bounds__(256, 2)
fused_kernel(const float* __restrict__ vt,
             const float* __restrict__ W,
             const float* __restrict__ bias,
             const void* __restrict__ ids_raw,
             const float* __restrict__ table,
             float* __restrict__ out) {
    __shared__ float As[GBK][GBM];   // [k][m]  8 KB
    __shared__ float Bs[GBK][GBN];   // [k][n]  8 KB
    __shared__ int   arow[GBM];

    int tid = threadIdx.x;           // 256

    if (blockIdx.x >= NGEMM) {
        // ------------------ embedding gather ------------------
        int r = blockIdx.x - NGEMM;      // 0..32767
        int b = r >> 9, t = r & 511;
        long long id;
        if (g_is64) id = ((const long long*)ids_raw)[r];
        else        id = (long long)((const int*)ids_raw)[r];
        const float4* src = (const float4*)(table + (size_t)id * DL);
        float4* dst = (float4*)(out + (size_t)(b * OUT_S + TOPK + t) * DL);
        #pragma unroll
        for (int i = 0; i < 4; i++) dst[tid + i * 256] = src[tid + i * 256];
        return;
    }

    // ------------------ GEMM tile ------------------
    int mblk = blockIdx.x >> 5;          // 16 m-blocks
    int nblk = blockIdx.x & 31;          // 32 n-blocks
    int m0 = mblk * GBM;
    int n0 = nblk * GBN;

    if (tid < GBM) {
        int m = m0 + tid;
        arow[tid] = ((m >> 5) * S_SZ + 1 + g_topk[m]) * DV;
    }
    __syncthreads();

    int ty = tid >> 4, tx = tid & 15;    // 16x16 threads, 8x8 outputs each
    u64 acc[8][4];
    #pragma unroll
    for (int i = 0; i < 8; i++)
        #pragma unroll
        for (int j = 0; j < 4; j++) acc[i][j] = 0ull;

    for (int kt = 0; kt < DV; kt += GBK) {
        // A tile: 128 rows x 16 k (gathered rows). 512 float4, 2 per thread.
        #pragma unroll
        for (int i = 0; i < 2; i++) {
            int f = tid + i * 256;
            int row = f >> 2, kc = (f & 3) * 4;
            float4 v = *(const float4*)(vt + arow[row] + kt + kc);
            As[kc + 0][row] = v.x; As[kc + 1][row] = v.y;
            As[kc + 2][row] = v.z; As[kc + 3][row] = v.w;
        }
        // B tile: 16 k x 128 n. 512 float4, 2 per thread.
        #pragma unroll
        for (int i = 0; i < 2; i++) {
            int f = tid + i * 256;
            int kr = f >> 5, nc = (f & 31) * 4;
            *(float4*)&Bs[kr][nc] = *(const float4*)(W + (size_t)(kt + kr) * DL + n0 + nc);
        }
        __syncthreads();

        #pragma unroll
        for (int k = 0; k < GBK; k++) {
            float4 a0 = *(const float4*)&As[k][ty * 8];
            float4 a1 = *(const float4*)&As[k][ty * 8 + 4];
            float4 b0 = *(const float4*)&Bs[k][tx * 8];
            float4 b1 = *(const float4*)&Bs[k][tx * 8 + 4];
            u64 bp0 = pack2(b0.x, b0.y);
            u64 bp1 = pack2(b0.z, b0.w);
            u64 bp2 = pack2(b1.x, b1.y);
            u64 bp3 = pack2(b1.z, b1.w);
            float av[8] = {a0.x, a0.y, a0.z, a0.w, a1.x, a1.y, a1.z, a1.w};
            #pragma unroll
            for (int i = 0; i < 8; i++) {
                u64 ad = pack2(av[i], av[i]);
                ffma2(acc[i][0], ad, bp0);
                ffma2(acc[i][1], ad, bp1);
                ffma2(acc[i][2], ad, bp2);
                ffma2(acc[i][3], ad, bp3);
            }
        }
        __syncthreads();
    }

    float4 bias0 = *(const float4*)(bias + n0 + tx * 8);
    float4 bias1 = *(const float4*)(bias + n0 + tx * 8 + 4);
    #pragma unroll
    for (int i = 0; i < 8; i++) {
        int m = m0 + ty * 8 + i;
        int b = m >> 5, kk = m & 31;
        float* orow = out + (size_t)(b * OUT_S + kk) * DL + n0 + tx * 8;
        float2 c0 = unpack2(acc[i][0]);
        float2 c1 = unpack2(acc[i][1]);
        float2 c2 = unpack2(acc[i][2]);
        float2 c3 = unpack2(acc[i][3]);
        float4 r0, r1;
        r0.x = c0.x + bias0.x; r0.y = c0.y + bias0.y;
        r0.z = c1.x + bias0.z; r0.w = c1.y + bias0.w;
        r1.x = c2.x + bias1.x; r1.y = c2.y + bias1.y;
        r1.z = c3.x + bias1.z; r1.w = c3.y + bias1.w;
        *(float4*)orow = r0;
        *(float4*)(orow + 4) = r1;
    }
}

// ---------------------------------------------------------------------------
// kernel_launch
// metadata order: vision_tokens, input_ids, ln_gamma, ln_beta, scorer_w,
//                 scorer_b, proj_w, proj_b, embed_table
// ---------------------------------------------------------------------------
extern "C" void kernel_launch(void* const* d_in, const int* in_sizes, int n_in,
                              void* d_out, int out_size) {
    const float* vision_tokens = (const float*)d_in[0];
    const void*  input_ids     = d_in[1];
    const float* ln_gamma      = (const float*)d_in[2];
    const float* ln_beta       = (const float*)d_in[3];
    const float* scorer_w      = (const float*)d_in[4];
    // d_in[5] scorer_b: constant shift, irrelevant to top-k ordering
    const float* proj_w        = (const float*)d_in[6];
    const float* proj_b        = (const float*)d_in[7];
    const float* embed_table   = (const float*)d_in[8];
    float* out = (float*)d_out;

    sniff_kernel<<<1, 32>>>((const int*)input_ids);
    scores_kernel<<<B_SZ * P_SZ, 128>>>(vision_tokens, ln_gamma, ln_beta, scorer_w);
    topk_kernel<<<B_SZ, 256>>>();
    fused_kernel<<<NGEMM + NGATHER, 256>>>(vision_tokens, proj_w, proj_b,
                                           input_ids, embed_table, out);
}

// round 3
// speedup vs baseline: 1.4380x; 1.2803x over previous
#include <cuda_runtime.h>
#include <cuda_bf16.h>
#include <float.h>
#include <stdint.h>

// ---------------------------------------------------------------------------
// Problem constants (fixed shapes for SparseVLMModel_59725815218738)
// ---------------------------------------------------------------------------
#define B_SZ    64
#define S_SZ    197
#define P_SZ    196      // patch tokens (skip CLS)
#define T_SZ    512
#define DV      768
#define DL      4096
#define TOPK    32
#define OUT_S   (TOPK + T_SZ)   // 544
#define LN_EPS  1e-5f

// Scratch (no cudaMalloc allowed)
__device__ float g_scores[B_SZ * P_SZ];
__device__ int   g_topk[B_SZ * TOPK];
__device__ int   g_is64;

typedef unsigned long long u64;

__device__ __forceinline__ u64 pack2(float lo, float hi) {
    u64 r; asm("mov.b64 %0, {%1, %2};" : "=l"(r) : "f"(lo), "f"(hi)); return r;
}
__device__ __forceinline__ void ffma2(u64& c, u64 a, u64 b) {
    asm("fma.rn.f32x2 %0, %1, %2, %0;" : "+l"(c) : "l"(a), "l"(b));
}
__device__ __forceinline__ float2 unpack2(u64 v) {
    float2 f; asm("mov.b64 {%0, %1}, %2;" : "=f"(f.x), "=f"(f.y) : "l"(v)); return f;
}

// ---------------------------------------------------------------------------
// 0. Sniff int32 vs int64 ids. ids < 32000, so int64 => every odd word == 0.
// ---------------------------------------------------------------------------
__global__ void sniff_kernel(const int* __restrict__ ids) {
    unsigned nz = __ballot_sync(0xffffffffu, ids[2 * threadIdx.x + 1] != 0);
    if (threadIdx.x == 0) g_is64 = (nz == 0u) ? 1 : 0;
}

// ---------------------------------------------------------------------------
// 1. Scores: warp-per-row LayerNorm dot (ordering-equivalent form):
//    score_rank = rstd * (sum(x*g*w) - mean * sum(g*w))
//    fp32 is plenty: score gaps ~1e-4, fp32 reduce noise ~1e-6.
// ---------------------------------------------------------------------------
__global__ void __launch_bounds__(256)
scores_kernel(const float* __restrict__ vt,
              const float* __restrict__ gamma,
              const float* __restrict__ w) {
    int warp = (blockIdx.x * 256 + threadIdx.x) >> 5;   // 0..12543
    int lane = threadIdx.x & 31;
    if (warp >= B_SZ * P_SZ) return;
    int b = warp / P_SZ, s = warp % P_SZ;
    const float4* x4 = (const float4*)(vt + (size_t)(b * S_SZ + 1 + s) * DV);
    const float4* g4 = (const float4*)gamma;
    const float4* w4 = (const float4*)w;

    float s1 = 0.f, s2 = 0.f, sgw = 0.f, cgw = 0.f;
    #pragma unroll
    for (int i = 0; i < 6; i++) {
        int idx = lane + i * 32;          // 192 float4 per row
        float4 xv = x4[idx];
        float4 gv = g4[idx];
        float4 wv = w4[idx];
        float gw0 = gv.x * wv.x, gw1 = gv.y * wv.y, gw2 = gv.z * wv.z, gw3 = gv.w * wv.w;
        s1 += xv.x + xv.y + xv.z + xv.w;
        s2 += xv.x * xv.x + xv.y * xv.y + xv.z * xv.z + xv.w * xv.w;
        sgw += xv.x * gw0 + xv.y * gw1 + xv.z * gw2 + xv.w * gw3;
        cgw += gw0 + gw1 + gw2 + gw3;
    }
    #pragma unroll
    for (int st = 16; st > 0; st >>= 1) {
        s1  += __shfl_xor_sync(0xffffffffu, s1, st);
        s2  += __shfl_xor_sync(0xffffffffu, s2, st);
        sgw += __shfl_xor_sync(0xffffffffu, sgw, st);
        cgw += __shfl_xor_sync(0xffffffffu, cgw, st);
    }
    if (lane == 0) {
        float mean = s1 * (1.0f / DV);
        float var  = s2 * (1.0f / DV) - mean * mean;
        float rstd = rsqrtf(var + LN_EPS);
        g_scores[warp] = rstd * (sgw - mean * cgw);
    }
}

// ---------------------------------------------------------------------------
// 2. Top-32 per batch, descending, stable (lower index wins ties) = lax.top_k
// ---------------------------------------------------------------------------
__global__ void topk_kernel() {
    __shared__ float sc[256];
    __shared__ float rv[256];
    __shared__ int   ri[256];
    int b = blockIdx.x, t = threadIdx.x;
    sc[t] = (t < P_SZ) ? g_scores[b * P_SZ + t] : -FLT_MAX;
    __syncthreads();
    for (int k = 0; k < TOPK; k++) {
        rv[t] = sc[t]; ri[t] = t;
        __syncthreads();
        for (int st = 128; st > 0; st >>= 1) {
            if (t < st) {
                float v2 = rv[t + st]; int i2 = ri[t + st];
                if (v2 > rv[t] || (v2 == rv[t] && i2 < ri[t])) { rv[t] = v2; ri[t] = i2; }
            }
            __syncthreads();
        }
        if (t == 0) {
            g_topk[b * TOPK + k] = ri[0];
            sc[ri[0]] = -FLT_MAX;
        }
        __syncthreads();
    }
}

// ---------------------------------------------------------------------------
// 3. Visual GEMM: out[b*544+k, :] = gather(vt)[b,k,:768] @ W[768,4096] + bias
//    128x128x32 tile, 256 threads, 8x8 per thread, FFMA2 inner loop.
// ---------------------------------------------------------------------------
#define GBM 128
#define GBN 128
#define GBK 32
#define NGEMM ((B_SZ * TOPK / GBM) * (DL / GBN))   // 16 * 32 = 512

__global__ void __launch_bounds__(256, 2)
gemm_kernel(const float* __restrict__ vt,
            const float* __restrict__ W,
            const float* __restrict__ bias,
            float* __restrict__ out) {
    __shared__ float As[GBK][GBM];   // [k][m]  16 KB
    __shared__ float Bs[GBK][GBN];   // [k][n]  16 KB
    __shared__ int   arow[GBM];

    int tid = threadIdx.x;           // 256
    int mblk = blockIdx.x >> 5;      // 16 m-blocks
    int nblk = blockIdx.x & 31;      // 32 n-blocks
    int m0 = mblk * GBM;
    int n0 = nblk * GBN;

    if (tid < GBM) {
        int m = m0 + tid;
        arow[tid] = ((m >> 5) * S_SZ + 1 + g_topk[m]) * DV;
    }
    __syncthreads();

    int ty = tid >> 4, tx = tid & 15;    // 16x16 threads, 8x8 outputs each
    u64 acc[8][4];
    #pragma unroll
    for (int i = 0; i < 8; i++)
        #pragma unroll
        for (int j = 0; j < 4; j++) acc[i][j] = 0ull;

    for (int kt = 0; kt < DV; kt += GBK) {
        // A tile: 128 rows x 32 k (gathered rows). 1024 float4, 4 per thread.
        #pragma unroll
        for (int i = 0; i < 4; i++) {
            int f = tid + i * 256;
            int row = f >> 3, kc = (f & 7) * 4;
            float4 v = *(const float4*)(vt + arow[row] + kt + kc);
            As[kc + 0][row] = v.x; As[kc + 1][row] = v.y;
            As[kc + 2][row] = v.z; As[kc + 3][row] = v.w;
        }
        // B tile: 32 k x 128 n. 1024 float4, 4 per thread.
        #pragma unroll
        for (int i = 0; i < 4; i++) {
            int f = tid + i * 256;
            int kr = f >> 5, nc = (f & 31) * 4;
            *(float4*)&Bs[kr][nc] = *(const float4*)(W + (size_t)(kt + kr) * DL + n0 + nc);
        }
        __syncthreads();

        #pragma unroll
        for (int k = 0; k < GBK; k++) {
            float4 a0 = *(const float4*)&As[k][ty * 8];
            float4 a1 = *(const float4*)&As[k][ty * 8 + 4];
            float4 b0 = *(const float4*)&Bs[k][tx * 8];
            float4 b1 = *(const float4*)&Bs[k][tx * 8 + 4];
            u64 bp0 = pack2(b0.x, b0.y);
            u64 bp1 = pack2(b0.z, b0.w);
            u64 bp2 = pack2(b1.x, b1.y);
            u64 bp3 = pack2(b1.z, b1.w);
            float av[8] = {a0.x, a0.y, a0.z, a0.w, a1.x, a1.y, a1.z, a1.w};
            #pragma unroll
            for (int i = 0; i < 8; i++) {
                u64 ad = pack2(av[i], av[i]);
                ffma2(acc[i][0], ad, bp0);
                ffma2(acc[i][1], ad, bp1);
                ffma2(acc[i][2], ad, bp2);
                ffma2(acc[i][3], ad, bp3);
            }
        }
        __syncthreads();
    }

    float4 bias0 = *(const float4*)(bias + n0 + tx * 8);
    float4 bias1 = *(const float4*)(bias + n0 + tx * 8 + 4);
    #pragma unroll
    for (int i = 0; i < 8; i++) {
        int m = m0 + ty * 8 + i;
        int b = m >> 5, kk = m & 31;
        float* orow = out + (size_t)(b * OUT_S + kk) * DL + n0 + tx * 8;
        float2 c0 = unpack2(acc[i][0]);
        float2 c1 = unpack2(acc[i][1]);
        float2 c2 = unpack2(acc[i][2]);
        float2 c3 = unpack2(acc[i][3]);
        float4 r0, r1;
        r0.x = c0.x + bias0.x; r0.y = c0.y + bias0.y;
        r0.z = c1.x + bias0.z; r0.w = c1.y + bias0.w;
        r1.x = c2.x + bias1.x; r1.y = c2.y + bias1.y;
        r1.z = c3.x + bias1.z; r1.w = c3.y + bias1.w;
        *(float4*)orow = r0;
        *(float4*)(orow + 4) = r1;
    }
}

// ---------------------------------------------------------------------------
// 4. Embedding gather (dedicated, low-register, high-occupancy kernel)
// ---------------------------------------------------------------------------
__global__ void __launch_bounds__(256)
gather_kernel(const void* __restrict__ ids_raw,
              const float* __restrict__ table,
              float* __restrict__ out) {
    int r = blockIdx.x;               // 0..32767
    int b = r >> 9, t = r & 511;
    long long id;
    if (g_is64) id = ((const long long*)ids_raw)[r];
    else        id = (long long)((const int*)ids_raw)[r];

    const float4* src = (const float4*)(table + (size_t)id * DL);
    float4* dst = (float4*)(out + (size_t)(b * OUT_S + TOPK + t) * DL);
    int tid = threadIdx.x;            // 256 threads x 4 float4 = 4096 floats
    #pragma unroll
    for (int i = 0; i < 4; i++) dst[tid + i * 256] = src[tid + i * 256];
}

// ---------------------------------------------------------------------------
// kernel_launch: fork the DRAM-bound gather onto a second stream so it
// co-runs with the FMA-bound scores/topk/GEMM chain. Event fork/join is
// graph-capturable; streams/events are host-side objects (no device alloc).
// metadata order: vision_tokens, input_ids, ln_gamma, ln_beta, scorer_w,
//                 scorer_b, proj_w, proj_b, embed_table
// ---------------------------------------------------------------------------
extern "C" void kernel_launch(void* const* d_in, const int* in_sizes, int n_in,
                              void* d_out, int out_size) {
    const float* vision_tokens = (const float*)d_in[0];
    const void*  input_ids     = d_in[1];
    const float* ln_gamma      = (const float*)d_in[2];
    const float* scorer_w      = (const float*)d_in[4];
    // d_in[3] ln_beta, d_in[5] scorer_b: constant shifts, irrelevant to ordering
    const float* proj_w        = (const float*)d_in[6];
    const float* proj_b        = (const float*)d_in[7];
    const float* embed_table   = (const float*)d_in[8];
    float* out = (float*)d_out;

    static cudaStream_t s2 = nullptr;
    static cudaEvent_t eFork = nullptr, eJoin = nullptr;
    if (s2 == nullptr) {
        cudaStreamCreateWithFlags(&s2, cudaStreamNonBlocking);
        cudaEventCreateWithFlags(&eFork, cudaEventDisableTiming);
        cudaEventCreateWithFlags(&eJoin, cudaEventDisableTiming);
    }

    // main (capture) stream: sniff first (gather depends on g_is64)
    sniff_kernel<<<1, 32>>>((const int*)input_ids);
    cudaEventRecord(eFork, 0);
    cudaStreamWaitEvent(s2, eFork, 0);

    // branch B (stream s2): DRAM-bound embedding gather
    gather_kernel<<<B_SZ * T_SZ, 256, 0, s2>>>(input_ids, embed_table, out);
    cudaEventRecord(eJoin, s2);

    // branch A (main stream): FMA-bound chain
    scores_kernel<<<(B_SZ * P_SZ * 32 + 255) / 256, 256>>>(vision_tokens, ln_gamma, scorer_w);
    topk_kernel<<<B_SZ, 256>>>();
    gemm_kernel<<<NGEMM, 256>>>(vision_tokens, proj_w, proj_b, out);

    // join
    cudaStreamWaitEvent(0, eJoin, 0);
}

// round 4
// speedup vs baseline: 1.4414x; 1.0024x over previous
#include <cuda_runtime.h>
#include <cuda_bf16.h>
#include <float.h>
#include <stdint.h>

// ---------------------------------------------------------------------------
// Problem constants (fixed shapes for SparseVLMModel_59725815218738)
// ---------------------------------------------------------------------------
#define B_SZ    64
#define S_SZ    197
#define P_SZ    196      // patch tokens (skip CLS)
#define T_SZ    512
#define DV      768
#define DL      4096
#define TOPK    32
#define OUT_S   (TOPK + T_SZ)   // 544
#define LN_EPS  1e-5f

// Scratch (no cudaMalloc allowed)
__device__ float g_scores[B_SZ * P_SZ];
__device__ int   g_topk[B_SZ * TOPK];
__device__ int   g_is64;

typedef unsigned long long u64;

__device__ __forceinline__ u64 pack2(float lo, float hi) {
    u64 r; asm("mov.b64 %0, {%1, %2};" : "=l"(r) : "f"(lo), "f"(hi)); return r;
}
__device__ __forceinline__ void ffma2(u64& c, u64 a, u64 b) {
    asm("fma.rn.f32x2 %0, %1, %2, %0;" : "+l"(c) : "l"(a), "l"(b));
}
__device__ __forceinline__ float2 unpack2(u64 v) {
    float2 f; asm("mov.b64 {%0, %1}, %2;" : "=f"(f.x), "=f"(f.y) : "l"(v)); return f;
}

// ---------------------------------------------------------------------------
// 0. Sniff int32 vs int64 ids. ids < 32000, so int64 => every odd word == 0.
// ---------------------------------------------------------------------------
__global__ void sniff_kernel(const int* __restrict__ ids) {
    unsigned nz = __ballot_sync(0xffffffffu, ids[2 * threadIdx.x + 1] != 0);
    if (threadIdx.x == 0) g_is64 = (nz == 0u) ? 1 : 0;
}

// ---------------------------------------------------------------------------
// 1. Scores: warp-per-row LayerNorm dot (ordering-equivalent form):
//    score_rank = rstd * (sum(x*g*w) - mean * sum(g*w))
//    fp32 is plenty: score gaps ~1e-4, fp32 reduce noise ~1e-6.
// ---------------------------------------------------------------------------
__global__ void __launch_bounds__(256)
scores_kernel(const float* __restrict__ vt,
              const float* __restrict__ gamma,
              const float* __restrict__ w) {
    int warp = (blockIdx.x * 256 + threadIdx.x) >> 5;   // 0..12543
    int lane = threadIdx.x & 31;
    if (warp >= B_SZ * P_SZ) return;
    int b = warp / P_SZ, s = warp % P_SZ;
    const float4* x4 = (const float4*)(vt + (size_t)(b * S_SZ + 1 + s) * DV);
    const float4* g4 = (const float4*)gamma;
    const float4* w4 = (const float4*)w;

    float s1 = 0.f, s2 = 0.f, sgw = 0.f, cgw = 0.f;
    #pragma unroll
    for (int i = 0; i < 6; i++) {
        int idx = lane + i * 32;          // 192 float4 per row
        float4 xv = x4[idx];
        float4 gv = g4[idx];
        float4 wv = w4[idx];
        float gw0 = gv.x * wv.x, gw1 = gv.y * wv.y, gw2 = gv.z * wv.z, gw3 = gv.w * wv.w;
        s1 += xv.x + xv.y + xv.z + xv.w;
        s2 += xv.x * xv.x + xv.y * xv.y + xv.z * xv.z + xv.w * xv.w;
        sgw += xv.x * gw0 + xv.y * gw1 + xv.z * gw2 + xv.w * gw3;
        cgw += gw0 + gw1 + gw2 + gw3;
    }
    #pragma unroll
    for (int st = 16; st > 0; st >>= 1) {
        s1  += __shfl_xor_sync(0xffffffffu, s1, st);
        s2  += __shfl_xor_sync(0xffffffffu, s2, st);
        sgw += __shfl_xor_sync(0xffffffffu, sgw, st);
        cgw += __shfl_xor_sync(0xffffffffu, cgw, st);
    }
    if (lane == 0) {
        float mean = s1 * (1.0f / DV);
        float var  = s2 * (1.0f / DV) - mean * mean;
        float rstd = rsqrtf(var + LN_EPS);
        g_scores[warp] = rstd * (sgw - mean * cgw);
    }
}

// ---------------------------------------------------------------------------
// 2. Top-32 per batch, descending, stable (lower index wins ties) = lax.top_k
// ---------------------------------------------------------------------------
__global__ void topk_kernel() {
    __shared__ float sc[256];
    __shared__ float rv[256];
    __shared__ int   ri[256];
    int b = blockIdx.x, t = threadIdx.x;
    sc[t] = (t < P_SZ) ? g_scores[b * P_SZ + t] : -FLT_MAX;
    __syncthreads();
    for (int k = 0; k < TOPK; k++) {
        rv[t] = sc[t]; ri[t] = t;
        __syncthreads();
        for (int st = 128; st > 0; st >>= 1) {
            if (t < st) {
                float v2 = rv[t + st]; int i2 = ri[t + st];
                if (v2 > rv[t] || (v2 == rv[t] && i2 < ri[t])) { rv[t] = v2; ri[t] = i2; }
            }
            __syncthreads();
        }
        if (t == 0) {
            g_topk[b * TOPK + k] = ri[0];
            sc[ri[0]] = -FLT_MAX;
        }
        __syncthreads();
    }
}

// ---------------------------------------------------------------------------
// 3. Visual GEMM: out[b*544+k, :] = gather(vt)[b,k,:768] @ W[768,4096] + bias
//    128x128x32 tile, 256 threads, 8x8 per thread, FFMA2 inner loop.
// ---------------------------------------------------------------------------
#define GBM 128
#define GBN 128
#define GBK 32
#define NGEMM ((B_SZ * TOPK / GBM) * (DL / GBN))   // 16 * 32 = 512

__global__ void __launch_bounds__(256, 2)
gemm_kernel(const float* __restrict__ vt,
            const float* __restrict__ W,
            const float* __restrict__ bias,
            float* __restrict__ out) {
    __shared__ float As[GBK][GBM];   // [k][m]  16 KB
    __shared__ float Bs[GBK][GBN];   // [k][n]  16 KB
    __shared__ int   arow[GBM];

    int tid = threadIdx.x;           // 256
    int mblk = blockIdx.x >> 5;      // 16 m-blocks
    int nblk = blockIdx.x & 31;      // 32 n-blocks
    int m0 = mblk * GBM;
    int n0 = nblk * GBN;

    if (tid < GBM) {
        int m = m0 + tid;
        arow[tid] = ((m >> 5) * S_SZ + 1 + g_topk[m]) * DV;
    }
    __syncthreads();

    int ty = tid >> 4, tx = tid & 15;    // 16x16 threads, 8x8 outputs each
    u64 acc[8][4];
    #pragma unroll
    for (int i = 0; i < 8; i++)
        #pragma unroll
        for (int j = 0; j < 4; j++) acc[i][j] = 0ull;

    for (int kt = 0; kt < DV; kt += GBK) {
        // A tile: 128 rows x 32 k (gathered rows). 1024 float4, 4 per thread.
        #pragma unroll
        for (int i = 0; i < 4; i++) {
            int f = tid + i * 256;
            int row = f >> 3, kc = (f & 7) * 4;
            float4 v = *(const float4*)(vt + arow[row] + kt + kc);
            As[kc + 0][row] = v.x; As[kc + 1][row] = v.y;
            As[kc + 2][row] = v.z; As[kc + 3][row] = v.w;
        }
        // B tile: 32 k x 128 n. 1024 float4, 4 per thread.
        #pragma unroll
        for (int i = 0; i < 4; i++) {
            int f = tid + i * 256;
            int kr = f >> 5, nc = (f & 31) * 4;
            *(float4*)&Bs[kr][nc] = *(const float4*)(W + (size_t)(kt + kr) * DL + n0 + nc);
        }
        __syncthreads();

        #pragma unroll
        for (int k = 0; k < GBK; k++) {
            float4 a0 = *(const float4*)&As[k][ty * 8];
            float4 a1 = *(const float4*)&As[k][ty * 8 + 4];
            float4 b0 = *(const float4*)&Bs[k][tx * 8];
            float4 b1 = *(const float4*)&Bs[k][tx * 8 + 4];
            u64 bp0 = pack2(b0.x, b0.y);
            u64 bp1 = pack2(b0.z, b0.w);
            u64 bp2 = pack2(b1.x, b1.y);
            u64 bp3 = pack2(b1.z, b1.w);
            float av[8] = {a0.x, a0.y, a0.z, a0.w, a1.x, a1.y, a1.z, a1.w};
            #pragma unroll
            for (int i = 0; i < 8; i++) {
                u64 ad = pack2(av[i], av[i]);
                ffma2(acc[i][0], ad, bp0);
                ffma2(acc[i][1], ad, bp1);
                ffma2(acc[i][2], ad, bp2);
                ffma2(acc[i][3], ad, bp3);
            }
        }
        __syncthreads();
    }

    float4 bias0 = *(const float4*)(bias + n0 + tx * 8);
    float4 bias1 = *(const float4*)(bias + n0 + tx * 8 + 4);
    #pragma unroll
    for (int i = 0; i < 8; i++) {
        int m = m0 + ty * 8 + i;
        int b = m >> 5, kk = m & 31;
        float* orow = out + (size_t)(b * OUT_S + kk) * DL + n0 + tx * 8;
        float2 c0 = unpack2(acc[i][0]);
        float2 c1 = unpack2(acc[i][1]);
        float2 c2 = unpack2(acc[i][2]);
        float2 c3 = unpack2(acc[i][3]);
        float4 r0, r1;
        r0.x = c0.x + bias0.x; r0.y = c0.y + bias0.y;
        r0.z = c1.x + bias0.z; r0.w = c1.y + bias0.w;
        r1.x = c2.x + bias1.x; r1.y = c2.y + bias1.y;
        r1.z = c3.x + bias1.z; r1.w = c3.y + bias1.w;
        *(float4*)orow = r0;
        *(float4*)(orow + 4) = r1;
    }
}

// ---------------------------------------------------------------------------
// 4. Embedding gather (dedicated, low-register, high-occupancy kernel)
// ---------------------------------------------------------------------------
__global__ void __launch_bounds__(256)
gather_kernel(const void* __restrict__ ids_raw,
              const float* __restrict__ table,
              float* __restrict__ out) {
    int r = blockIdx.x;               // 0..32767
    int b = r >> 9, t = r & 511;
    long long id;
    if (g_is64) id = ((const long long*)ids_raw)[r];
    else        id = (long long)((const int*)ids_raw)[r];

    const float4* src = (const float4*)(table + (size_t)id * DL);
    float4* dst = (float4*)(out + (size_t)(b * OUT_S + TOPK + t) * DL);
    int tid = threadIdx.x;            // 256 threads x 4 float4 = 4096 floats
    #pragma unroll
    for (int i = 0; i < 4; i++) dst[tid + i * 256] = src[tid + i * 256];
}

// ---------------------------------------------------------------------------
// kernel_launch: fork the DRAM-bound gather onto a second stream so it
// co-runs with the FMA-bound scores/topk/GEMM chain. Event fork/join is
// graph-capturable; streams/events are host-side objects (no device alloc).
// metadata order: vision_tokens, input_ids, ln_gamma, ln_beta, scorer_w,
//                 scorer_b, proj_w, proj_b, embed_table
// ---------------------------------------------------------------------------
extern "C" void kernel_launch(void* const* d_in, const int* in_sizes, int n_in,
                              void* d_out, int out_size) {
    const float* vision_tokens = (const float*)d_in[0];
    const void*  input_ids     = d_in[1];
    const float* ln_gamma      = (const float*)d_in[2];
    const float* scorer_w      = (const float*)d_in[4];
    // d_in[3] ln_beta, d_in[5] scorer_b: constant shifts, irrelevant to ordering
    const float* proj_w        = (const float*)d_in[6];
    const float* proj_b        = (const float*)d_in[7];
    const float* embed_table   = (const float*)d_in[8];
    float* out = (float*)d_out;

    static cudaStream_t s2 = nullptr;
    static cudaEvent_t eFork = nullptr, eJoin = nullptr;
    if (s2 == nullptr) {
        cudaStreamCreateWithFlags(&s2, cudaStreamNonBlocking);
        cudaEventCreateWithFlags(&eFork, cudaEventDisableTiming);
        cudaEventCreateWithFlags(&eJoin, cudaEventDisableTiming);
    }

    // main (capture) stream: sniff first (gather depends on g_is64)
    sniff_kernel<<<1, 32>>>((const int*)input_ids);
    cudaEventRecord(eFork, 0);
    cudaStreamWaitEvent(s2, eFork, 0);

    // branch B (stream s2): DRAM-bound embedding gather
    gather_kernel<<<B_SZ * T_SZ, 256, 0, s2>>>(input_ids, embed_table, out);
    cudaEventRecord(eJoin, s2);

    // branch A (main stream): FMA-bound chain
    scores_kernel<<<(B_SZ * P_SZ * 32 + 255) / 256, 256>>>(vision_tokens, ln_gamma, scorer_w);
    topk_kernel<<<B_SZ, 256>>>();
    gemm_kernel<<<NGEMM, 256>>>(vision_tokens, proj_w, proj_b, out);

    // join
    cudaStreamWaitEvent(0, eJoin, 0);
}

// round 5
// speedup vs baseline: 1.4423x; 1.0006x over previous
#include <cuda_runtime.h>
#include <cuda_bf16.h>
#include <float.h>
#include <stdint.h>

// ---------------------------------------------------------------------------
// Problem constants (fixed shapes for SparseVLMModel_59725815218738)
// ---------------------------------------------------------------------------
#define B_SZ    64
#define S_SZ    197
#define P_SZ    196      // patch tokens (skip CLS)
#define T_SZ    512
#define DV      768
#define DL      4096
#define TOPK    32
#define OUT_S   (TOPK + T_SZ)   // 544
#define LN_EPS  1e-5f

// Scratch (no cudaMalloc allowed)
__device__ float g_scores[B_SZ * P_SZ];
__device__ int   g_topk[B_SZ * TOPK];
__device__ int   g_is64;

typedef unsigned long long u64;

__device__ __forceinline__ u64 pack2(float lo, float hi) {
    u64 r; asm("mov.b64 %0, {%1, %2};" : "=l"(r) : "f"(lo), "f"(hi)); return r;
}
__device__ __forceinline__ void ffma2(u64& c, u64 a, u64 b) {
    asm("fma.rn.f32x2 %0, %1, %2, %0;" : "+l"(c) : "l"(a), "l"(b));
}
__device__ __forceinline__ float2 unpack2(u64 v) {
    float2 f; asm("mov.b64 {%0, %1}, %2;" : "=f"(f.x), "=f"(f.y) : "l"(v)); return f;
}

// ---------------------------------------------------------------------------
// 0. Sniff int32 vs int64 ids. ids < 32000, so int64 => every odd word == 0.
// ---------------------------------------------------------------------------
__global__ void sniff_kernel(const int* __restrict__ ids) {
    unsigned nz = __ballot_sync(0xffffffffu, ids[2 * threadIdx.x + 1] != 0);
    if (threadIdx.x == 0) g_is64 = (nz == 0u) ? 1 : 0;
}

// ---------------------------------------------------------------------------
// 1. Scores: warp-per-row LayerNorm dot (ordering-equivalent form):
//    score_rank = rstd * (sum(x*g*w) - mean * sum(g*w))
//    fp32 is plenty: score gaps ~1e-4, fp32 reduce noise ~1e-6.
// ---------------------------------------------------------------------------
__global__ void __launch_bounds__(256)
scores_kernel(const float* __restrict__ vt,
              const float* __restrict__ gamma,
              const float* __restrict__ w) {
    int warp = (blockIdx.x * 256 + threadIdx.x) >> 5;   // 0..12543
    int lane = threadIdx.x & 31;
    if (warp >= B_SZ * P_SZ) return;
    int b = warp / P_SZ, s = warp % P_SZ;
    const float4* x4 = (const float4*)(vt + (size_t)(b * S_SZ + 1 + s) * DV);
    const float4* g4 = (const float4*)gamma;
    const float4* w4 = (const float4*)w;

    float s1 = 0.f, s2 = 0.f, sgw = 0.f, cgw = 0.f;
    #pragma unroll
    for (int i = 0; i < 6; i++) {
        int idx = lane + i * 32;          // 192 float4 per row
        float4 xv = x4[idx];
        float4 gv = g4[idx];
        float4 wv = w4[idx];
        float gw0 = gv.x * wv.x, gw1 = gv.y * wv.y, gw2 = gv.z * wv.z, gw3 = gv.w * wv.w;
        s1 += xv.x + xv.y + xv.z + xv.w;
        s2 += xv.x * xv.x + xv.y * xv.y + xv.z * xv.z + xv.w * xv.w;
        sgw += xv.x * gw0 + xv.y * gw1 + xv.z * gw2 + xv.w * gw3;
        cgw += gw0 + gw1 + gw2 + gw3;
    }
    #pragma unroll
    for (int st = 16; st > 0; st >>= 1) {
        s1  += __shfl_xor_sync(0xffffffffu, s1, st);
        s2  += __shfl_xor_sync(0xffffffffu, s2, st);
        sgw += __shfl_xor_sync(0xffffffffu, sgw, st);
        cgw += __shfl_xor_sync(0xffffffffu, cgw, st);
    }
    if (lane == 0) {
        float mean = s1 * (1.0f / DV);
        float var  = s2 * (1.0f / DV) - mean * mean;
        float rstd = rsqrtf(var + LN_EPS);
        g_scores[warp] = rstd * (sgw - mean * cgw);
    }
}

// ---------------------------------------------------------------------------
// 2. Top-32 per batch, descending, stable (lower index wins ties) = lax.top_k
// ---------------------------------------------------------------------------
__global__ void topk_kernel() {
    __shared__ float sc[256];
    __shared__ float rv[256];
    __shared__ int   ri[256];
    int b = blockIdx.x, t = threadIdx.x;
    sc[t] = (t < P_SZ) ? g_scores[b * P_SZ + t] : -FLT_MAX;
    __syncthreads();
    for (int k = 0; k < TOPK; k++) {
        rv[t] = sc[t]; ri[t] = t;
        __syncthreads();
        for (int st = 128; st > 0; st >>= 1) {
            if (t < st) {
                float v2 = rv[t + st]; int i2 = ri[t + st];
                if (v2 > rv[t] || (v2 == rv[t] && i2 < ri[t])) { rv[t] = v2; ri[t] = i2; }
            }
            __syncthreads();
        }
        if (t == 0) {
            g_topk[b * TOPK + k] = ri[0];
            sc[ri[0]] = -FLT_MAX;
        }
        __syncthreads();
    }
}

// ---------------------------------------------------------------------------
// 3. Visual GEMM: out[b*544+k, :] = gather(vt)[b,k,:768] @ W[768,4096] + bias
//    128x128x32 tile, 256 threads, 8x8 per thread, FFMA2 inner loop.
// ---------------------------------------------------------------------------
#define GBM 128
#define GBN 128
#define GBK 32
#define NGEMM ((B_SZ * TOPK / GBM) * (DL / GBN))   // 16 * 32 = 512

__global__ void __launch_bounds__(256, 2)
gemm_kernel(const float* __restrict__ vt,
            const float* __restrict__ W,
            const float* __restrict__ bias,
            float* __restrict__ out) {
    __shared__ float As[GBK][GBM];   // [k][m]  16 KB
    __shared__ float Bs[GBK][GBN];   // [k][n]  16 KB
    __shared__ int   arow[GBM];

    int tid = threadIdx.x;           // 256
    int mblk = blockIdx.x >> 5;      // 16 m-blocks
    int nblk = blockIdx.x & 31;      // 32 n-blocks
    int m0 = mblk * GBM;
    int n0 = nblk * GBN;

    if (tid < GBM) {
        int m = m0 + tid;
        arow[tid] = ((m >> 5) * S_SZ + 1 + g_topk[m]) * DV;
    }
    __syncthreads();

    int ty = tid >> 4, tx = tid & 15;    // 16x16 threads, 8x8 outputs each
    u64 acc[8][4];
    #pragma unroll
    for (int i = 0; i < 8; i++)
        #pragma unroll
        for (int j = 0; j < 4; j++) acc[i][j] = 0ull;

    for (int kt = 0; kt < DV; kt += GBK) {
        // A tile: 128 rows x 32 k (gathered rows). 1024 float4, 4 per thread.
        #pragma unroll
        for (int i = 0; i < 4; i++) {
            int f = tid + i * 256;
            int row = f >> 3, kc = (f & 7) * 4;
            float4 v = *(const float4*)(vt + arow[row] + kt + kc);
            As[kc + 0][row] = v.x; As[kc + 1][row] = v.y;
            As[kc + 2][row] = v.z; As[kc + 3][row] = v.w;
        }
        // B tile: 32 k x 128 n. 1024 float4, 4 per thread.
        #pragma unroll
        for (int i = 0; i < 4; i++) {
            int f = tid + i * 256;
            int kr = f >> 5, nc = (f & 31) * 4;
            *(float4*)&Bs[kr][nc] = *(const float4*)(W + (size_t)(kt + kr) * DL + n0 + nc);
        }
        __syncthreads();

        #pragma unroll
        for (int k = 0; k < GBK; k++) {
            float4 a0 = *(const float4*)&As[k][ty * 8];
            float4 a1 = *(const float4*)&As[k][ty * 8 + 4];
            float4 b0 = *(const float4*)&Bs[k][tx * 8];
            float4 b1 = *(const float4*)&Bs[k][tx * 8 + 4];
            u64 bp0 = pack2(b0.x, b0.y);
            u64 bp1 = pack2(b0.z, b0.w);
            u64 bp2 = pack2(b1.x, b1.y);
            u64 bp3 = pack2(b1.z, b1.w);
            float av[8] = {a0.x, a0.y, a0.z, a0.w, a1.x, a1.y, a1.z, a1.w};
            #pragma unroll
            for (int i = 0; i < 8; i++) {
                u64 ad = pack2(av[i], av[i]);
                ffma2(acc[i][0], ad, bp0);
                ffma2(acc[i][1], ad, bp1);
                ffma2(acc[i][2], ad, bp2);
                ffma2(acc[i][3], ad, bp3);
            }
        }
        __syncthreads();
    }

    float4 bias0 = *(const float4*)(bias + n0 + tx * 8);
    float4 bias1 = *(const float4*)(bias + n0 + tx * 8 + 4);
    #pragma unroll
    for (int i = 0; i < 8; i++) {
        int m = m0 + ty * 8 + i;
        int b = m >> 5, kk = m & 31;
        float* orow = out + (size_t)(b * OUT_S + kk) * DL + n0 + tx * 8;
        float2 c0 = unpack2(acc[i][0]);
        float2 c1 = unpack2(acc[i][1]);
        float2 c2 = unpack2(acc[i][2]);
        float2 c3 = unpack2(acc[i][3]);
        float4 r0, r1;
        r0.x = c0.x + bias0.x; r0.y = c0.y + bias0.y;
        r0.z = c1.x + bias0.z; r0.w = c1.y + bias0.w;
        r1.x = c2.x + bias1.x; r1.y = c2.y + bias1.y;
        r1.z = c3.x + bias1.z; r1.w = c3.y + bias1.w;
        *(float4*)orow = r0;
        *(float4*)(orow + 4) = r1;
    }
}

// ---------------------------------------------------------------------------
// 4. Embedding gather (dedicated, low-register, high-occupancy kernel)
// ---------------------------------------------------------------------------
__global__ void __launch_bounds__(256)
gather_kernel(const void* __restrict__ ids_raw,
              const float* __restrict__ table,
              float* __restrict__ out) {
    int r = blockIdx.x;               // 0..32767
    int b = r >> 9, t = r & 511;
    long long id;
    if (g_is64) id = ((const long long*)ids_raw)[r];
    else        id = (long long)((const int*)ids_raw)[r];

    const float4* src = (const float4*)(table + (size_t)id * DL);
    float4* dst = (float4*)(out + (size_t)(b * OUT_S + TOPK + t) * DL);
    int tid = threadIdx.x;            // 256 threads x 4 float4 = 4096 floats
    #pragma unroll
    for (int i = 0; i < 4; i++) dst[tid + i * 256] = src[tid + i * 256];
}

// ---------------------------------------------------------------------------
// kernel_launch: fork the DRAM-bound gather onto a second stream so it
// co-runs with the FMA-bound scores/topk/GEMM chain. Event fork/join is
// graph-capturable; streams/events are host-side objects (no device alloc).
// metadata order: vision_tokens, input_ids, ln_gamma, ln_beta, scorer_w,
//                 scorer_b, proj_w, proj_b, embed_table
// ---------------------------------------------------------------------------
extern "C" void kernel_launch(void* const* d_in, const int* in_sizes, int n_in,
                              void* d_out, int out_size) {
    const float* vision_tokens = (const float*)d_in[0];
    const void*  input_ids     = d_in[1];
    const float* ln_gamma      = (const float*)d_in[2];
    const float* scorer_w      = (const float*)d_in[4];
    // d_in[3] ln_beta, d_in[5] scorer_b: constant shifts, irrelevant to ordering
    const float* proj_w        = (const float*)d_in[6];
    const float* proj_b        = (const float*)d_in[7];
    const float* embed_table   = (const float*)d_in[8];
    float* out = (float*)d_out;

    static cudaStream_t s2 = nullptr;
    static cudaEvent_t eFork = nullptr, eJoin = nullptr;
    if (s2 == nullptr) {
        cudaStreamCreateWithFlags(&s2, cudaStreamNonBlocking);
        cudaEventCreateWithFlags(&eFork, cudaEventDisableTiming);
        cudaEventCreateWithFlags(&eJoin, cudaEventDisableTiming);
    }

    // main (capture) stream: sniff first (gather depends on g_is64)
    sniff_kernel<<<1, 32>>>((const int*)input_ids);
    cudaEventRecord(eFork, 0);
    cudaStreamWaitEvent(s2, eFork, 0);

    // branch B (stream s2): DRAM-bound embedding gather
    gather_kernel<<<B_SZ * T_SZ, 256, 0, s2>>>(input_ids, embed_table, out);
    cudaEventRecord(eJoin, s2);

    // branch A (main stream): FMA-bound chain
    scores_kernel<<<(B_SZ * P_SZ * 32 + 255) / 256, 256>>>(vision_tokens, ln_gamma, scorer_w);
    topk_kernel<<<B_SZ, 256>>>();
    gemm_kernel<<<NGEMM, 256>>>(vision_tokens, proj_w, proj_b, out);

    // join
    cudaStreamWaitEvent(0, eJoin, 0);
}

// round 7
// speedup vs baseline: 2.3517x; 1.6305x over previous
#include <cuda_runtime.h>
#include <cuda_bf16.h>
#include <float.h>
#include <stdint.h>

// ---------------------------------------------------------------------------
// Problem constants (fixed shapes for SparseVLMModel_59725815218738)
// ---------------------------------------------------------------------------
#define B_SZ    64
#define S_SZ    197
#define P_SZ    196
#define T_SZ    512
#define DV      768
#define DL      4096
#define TOPK    32
#define OUT_S   (TOPK + T_SZ)   // 544
#define LN_EPS  1e-5f

#define M_TOT   (B_SZ * TOPK)   // 2048
#define KC      (3 * DV)        // 2304: [Ahi|Ahi|Alo] x [Bhi|Blo|Bhi]
#define TM      128
#define TN      128
#define KCHUNK  64
#define NCHUNK  (KC / KCHUNK)   // 36

// Scratch (no cudaMalloc allowed)
__device__ float g_scores[B_SZ * P_SZ];
__device__ int   g_topk[M_TOT];
__device__ int   g_is64;
__device__ __align__(128) __nv_bfloat16 g_A[(size_t)M_TOT * KC]; // 9.4 MB
__device__ __align__(128) __nv_bfloat16 g_B[(size_t)DL * KC];    // 18.9 MB

__device__ __forceinline__ uint32_t smem_u32(const void* p) {
    uint32_t a;
    asm("{ .reg .u64 t; cvta.to.shared.u64 t, %1; cvt.u32.u64 %0, t; }" : "=r"(a) : "l"(p));
    return a;
}
__device__ __forceinline__ void ldsm4(uint32_t* r, uint32_t addr) {
    asm volatile("ldmatrix.sync.aligned.m8n8.x4.shared.b16 {%0,%1,%2,%3}, [%4];"
                 : "=r"(r[0]), "=r"(r[1]), "=r"(r[2]), "=r"(r[3]) : "r"(addr));
}
__device__ __forceinline__ void mma_bf16(float* c, const uint32_t* a,
                                         uint32_t b0, uint32_t b1) {
    asm volatile(
        "mma.sync.aligned.m16n8k16.row.col.f32.bf16.bf16.f32 "
        "{%0,%1,%2,%3}, {%4,%5,%6,%7}, {%8,%9}, {%0,%1,%2,%3};"
        : "+f"(c[0]), "+f"(c[1]), "+f"(c[2]), "+f"(c[3])
        : "r"(a[0]), "r"(a[1]), "r"(a[2]), "r"(a[3]), "r"(b0), "r"(b1));
}
#define SW128(x) ((x) ^ (((x) >> 3) & 0x70))

// ---------------------------------------------------------------------------
// 0. Sniff int32 vs int64 ids. ids < 32000, so int64 => every odd word == 0.
// ---------------------------------------------------------------------------
__global__ void sniff_kernel(const int* __restrict__ ids) {
    unsigned nz = __ballot_sync(0xffffffffu, ids[2 * threadIdx.x + 1] != 0);
    if (threadIdx.x == 0) g_is64 = (nz == 0u) ? 1 : 0;
}

// ---------------------------------------------------------------------------
// 1. Scores: warp-per-row LayerNorm dot (ordering-equivalent form)
// ---------------------------------------------------------------------------
__global__ void __launch_bounds__(256)
scores_kernel(const float* __restrict__ vt,
              const float* __restrict__ gamma,
              const float* __restrict__ w) {
    int warp = (blockIdx.x * 256 + threadIdx.x) >> 5;
    int lane = threadIdx.x & 31;
    if (warp >= B_SZ * P_SZ) return;
    int b = warp / P_SZ, s = warp % P_SZ;
    const float4* x4 = (const float4*)(vt + (size_t)(b * S_SZ + 1 + s) * DV);
    const float4* g4 = (const float4*)gamma;
    const float4* w4 = (const float4*)w;

    float s1 = 0.f, s2 = 0.f, sgw = 0.f, cgw = 0.f;
    #pragma unroll
    for (int i = 0; i < 6; i++) {
        int idx = lane + i * 32;
        float4 xv = x4[idx];
        float4 gv = g4[idx];
        float4 wv = w4[idx];
        float gw0 = gv.x * wv.x, gw1 = gv.y * wv.y, gw2 = gv.z * wv.z, gw3 = gv.w * wv.w;
        s1 += xv.x + xv.y + xv.z + xv.w;
        s2 += xv.x * xv.x + xv.y * xv.y + xv.z * xv.z + xv.w * xv.w;
        sgw += xv.x * gw0 + xv.y * gw1 + xv.z * gw2 + xv.w * gw3;
        cgw += gw0 + gw1 + gw2 + gw3;
    }
    #pragma unroll
    for (int st = 16; st > 0; st >>= 1) {
        s1  += __shfl_xor_sync(0xffffffffu, s1, st);
        s2  += __shfl_xor_sync(0xffffffffu, s2, st);
        sgw += __shfl_xor_sync(0xffffffffu, sgw, st);
        cgw += __shfl_xor_sync(0xffffffffu, cgw, st);
    }
    if (lane == 0) {
        float mean = s1 * (1.0f / DV);
        float var  = s2 * (1.0f / DV) - mean * mean;
        float rstd = rsqrtf(var + LN_EPS);
        g_scores[warp] = rstd * (sgw - mean * cgw);
    }
}

// ---------------------------------------------------------------------------
// 2. Top-32 per batch: warp-per-batch register argmax, stable ties.
// ---------------------------------------------------------------------------
__global__ void __launch_bounds__(256)
topk_kernel() {
    int warp = (blockIdx.x * 256 + threadIdx.x) >> 5;   // 0..63
    int lane = threadIdx.x & 31;
    if (warp >= B_SZ) return;
    float v[7];
    #pragma unroll
    for (int i = 0; i < 7; i++) {
        int idx = lane + i * 32;
        v[i] = (idx < P_SZ) ? g_scores[warp * P_SZ + idx] : -FLT_MAX;
    }
    for (int k = 0; k < TOPK; k++) {
        float best = -FLT_MAX; int bi = 0;
        #pragma unroll
        for (int i = 0; i < 7; i++)
            if (v[i] > best) { best = v[i]; bi = i; }    // ascending idx: stable
        int bidx = lane + bi * 32;
        #pragma unroll
        for (int st = 16; st > 0; st >>= 1) {
            float ov = __shfl_xor_sync(0xffffffffu, best, st);
            int   oi = __shfl_xor_sync(0xffffffffu, bidx, st);
            if (ov > best || (ov == best && oi < bidx)) { best = ov; bidx = oi; }
        }
        if (lane == 0) g_topk[warp * TOPK + k] = bidx;
        if ((bidx & 31) == lane) v[bidx >> 5] = -FLT_MAX;
    }
}

// ---------------------------------------------------------------------------
// 3a. Convert gathered A rows fp32 -> bf16 split [hi | hi | lo], K = 2304
// ---------------------------------------------------------------------------
__global__ void __launch_bounds__(128)
convertA_kernel(const float* __restrict__ vt) {
    int m = blockIdx.x;                // 0..2047
    int b = m >> 5;
    size_t base = (size_t)(b * S_SZ + 1 + g_topk[m]) * DV;
    __nv_bfloat16* rowA = g_A + (size_t)m * KC;
    int t = threadIdx.x;
    #pragma unroll
    for (int i = 0; i < 3; i++) {
        int p = t + i * 128;           // pair 0..383
        float v0 = vt[base + 2 * p], v1 = vt[base + 2 * p + 1];
        __nv_bfloat16 h0 = __float2bfloat16(v0);
        __nv_bfloat16 h1 = __float2bfloat16(v1);
        __nv_bfloat162 hp; hp.x = h0; hp.y = h1;
        __nv_bfloat162 lp;
        lp.x = __float2bfloat16(v0 - __bfloat162float(h0));
        lp.y = __float2bfloat16(v1 - __bfloat162float(h1));
        *(__nv_bfloat162*)(rowA + 2 * p)          = hp;
        *(__nv_bfloat162*)(rowA + DV + 2 * p)     = hp;
        *(__nv_bfloat162*)(rowA + 2 * DV + 2 * p) = lp;
    }
}

// ---------------------------------------------------------------------------
// 3b. Convert+transpose proj_w [768,4096] -> g_B [4096][hi | lo | hi]
// ---------------------------------------------------------------------------
__global__ void __launch_bounds__(256)
convertB_kernel(const float* __restrict__ W) {
    __shared__ float tile[32][33];
    int n0 = blockIdx.x * 32;          // 128 blocks
    int k0 = blockIdx.y * 32;          // 24 blocks
    int t = threadIdx.x;
    #pragma unroll
    for (int i = 0; i < 4; i++) {
        int e = t + i * 256;
        int r = e >> 5, c = e & 31;
        tile[r][c] = W[(size_t)(k0 + r) * DL + n0 + c];
    }
    __syncthreads();
    #pragma unroll
    for (int i = 0; i < 2; i++) {
        int n = (t >> 4) + i * 16;
        int j = t & 15;
        float v0 = tile[2 * j][n], v1 = tile[2 * j + 1][n];
        __nv_bfloat16 h0 = __float2bfloat16(v0);
        __nv_bfloat16 h1 = __float2bfloat16(v1);
        __nv_bfloat162 hp; hp.x = h0; hp.y = h1;
        __nv_bfloat162 lp;
        lp.x = __float2bfloat16(v0 - __bfloat162float(h0));
        lp.y = __float2bfloat16(v1 - __bfloat162float(h1));
        __nv_bfloat16* rowB = g_B + (size_t)(n0 + n) * KC + k0 + 2 * j;
        *(__nv_bfloat162*)(rowB)          = hp;
        *(__nv_bfloat162*)(rowB + DV)     = lp;
        *(__nv_bfloat162*)(rowB + 2 * DV) = hp;
    }
}

// ---------------------------------------------------------------------------
// 4. mma.sync GEMM: D[2048,4096] = A'[2048,2304] @ B'[4096,2304]^T + bias
//    128x128 tile/CTA, 8 warps x (64x32), KCHUNK=64, SW128 smem,
//    register-prefetched double buffer, one __syncthreads per chunk.
// ---------------------------------------------------------------------------
#define SA_OFF(st) ((st) * 32768)
#define SB_OFF(st) (16384 + (st) * 32768)
#define SMEM_TOTAL 65536

__global__ void __launch_bounds__(256, 1)
gemm_mma_kernel(const float* __restrict__ bias, float* __restrict__ out) {
    extern __shared__ __align__(1024) char smem[];
    uint32_t sbase = smem_u32(smem);
    int tid = threadIdx.x;
    int wid = tid >> 5, lane = tid & 31;
    int mblk = blockIdx.x >> 5;          // 16
    int nblk = blockIdx.x & 31;          // 32
    int m0 = mblk * TM, n0 = nblk * TN;
    int wm = (wid & 1) * 64;             // warp M offset
    int wn = (wid >> 1) * 32;            // warp N offset

    // gmem load coords: 1024 x 16B per tile, 4 per thread
    int lrow = 0, lj = 0;                 // recomputed per i below
    const __nv_bfloat16* Abase = g_A + (size_t)m0 * KC;
    const __nv_bfloat16* Bbase = g_B + (size_t)n0 * KC;

    // ldmatrix lane addressing
    int q = lane >> 3, r8 = lane & 7;
    int qm = (q & 1) * 8;                // +8 rows for odd quads
    int qk = (q >> 1) * 16;              // +16B for k-half 1

    float acc[4][4][4];
    #pragma unroll
    for (int a = 0; a < 4; a++)
        #pragma unroll
        for (int b = 0; b < 4; b++)
            #pragma unroll
            for (int c = 0; c < 4; c++) acc[a][b][c] = 0.f;

    uint4 pa[4], pb[4];
    #define PREFETCH(cc) do { \
        const __nv_bfloat16* Ap = Abase + (cc) * KCHUNK; \
        const __nv_bfloat16* Bp = Bbase + (cc) * KCHUNK; \
        _Pragma("unroll") \
        for (int i = 0; i < 4; i++) { \
            int f = tid + i * 256; \
            lrow = f >> 3; lj = f & 7; \
            pa[i] = *(const uint4*)(Ap + (size_t)lrow * KC + lj * 8); \
            pb[i] = *(const uint4*)(Bp + (size_t)lrow * KC + lj * 8); \
        } \
    } while (0)
    #define STORE(st) do { \
        _Pragma("unroll") \
        for (int i = 0; i < 4; i++) { \
            int f = tid + i * 256; \
            lrow = f >> 3; lj = f & 7; \
            int off = SW128(lrow * 128 + lj * 16); \
            *(uint4*)(smem + SA_OFF(st) + off) = pa[i]; \
            *(uint4*)(smem + SB_OFF(st) + off) = pb[i]; \
        } \
    } while (0)

    PREFETCH(0);
    STORE(0);

    #pragma unroll 1
    for (int c = 0; c < NCHUNK; c++) {
        int st = c & 1;
        __syncthreads();                  // buf st filled, prev readers done
        if (c + 1 < NCHUNK) PREFETCH(c + 1);

        uint32_t abuf = sbase + SA_OFF(st);
        uint32_t bbuf = sbase + SB_OFF(st);
        #pragma unroll
        for (int ks = 0; ks < 4; ks++) {  // 4 x k16 per 64-chunk
            uint32_t afr[4][4], bfr[2][4];
            #pragma unroll
            for (int mt = 0; mt < 4; mt++)
                ldsm4(afr[mt], abuf + SW128((wm + mt * 16 + qm + r8) * 128 + ks * 32 + qk));
            #pragma unroll
            for (int nt = 0; nt < 2; nt++)
                ldsm4(bfr[nt], bbuf + SW128((wn + nt * 16 + qm + r8) * 128 + ks * 32 + qk));
            #pragma unroll
            for (int mt = 0; mt < 4; mt++)
                #pragma unroll
                for (int nf = 0; nf < 4; nf++) {
                    int nt = nf >> 1, half = nf & 1;
                    mma_bf16(acc[mt][nf], afr[mt], bfr[nt][half], bfr[nt][half + 2]);
                }
        }
        if (c + 1 < NCHUNK) STORE(st ^ 1);
    }

    // epilogue: C frag m16n8: c0,c1=(row g, col 2i,2i+1); c2,c3=(row g+8)
    int g = lane >> 2, i2 = (lane & 3) * 2;
    #pragma unroll
    for (int mt = 0; mt < 4; mt++) {
        #pragma unroll
        for (int rh = 0; rh < 2; rh++) {
            int m = m0 + wm + mt * 16 + rh * 8 + g;
            int b = m >> 5, kk = m & 31;
            float* orow = out + (size_t)(b * OUT_S + kk) * DL + n0 + wn;
            #pragma unroll
            for (int nf = 0; nf < 4; nf++) {
                int n = nf * 8 + i2;
                float2 bb = *(const float2*)(bias + n0 + wn + n);
                float2 o;
                o.x = acc[mt][nf][rh * 2 + 0] + bb.x;
                o.y = acc[mt][nf][rh * 2 + 1] + bb.y;
                *(float2*)(orow + n) = o;
            }
        }
    }
}

// ---------------------------------------------------------------------------
// 5. Embedding gather (DRAM-bound, dedicated high-occupancy kernel)
// ---------------------------------------------------------------------------
__global__ void __launch_bounds__(256)
gather_kernel(const void* __restrict__ ids_raw,
              const float* __restrict__ table,
              float* __restrict__ out) {
    int r = blockIdx.x;               // 0..32767
    int b = r >> 9, t = r & 511;
    long long id;
    if (g_is64) id = ((const long long*)ids_raw)[r];
    else        id = (long long)((const int*)ids_raw)[r];

    const float4* src = (const float4*)(table + (size_t)id * DL);
    float4* dst = (float4*)(out + (size_t)(b * OUT_S + TOPK + t) * DL);
    int tid = threadIdx.x;
    #pragma unroll
    for (int i = 0; i < 4; i++) dst[tid + i * 256] = src[tid + i * 256];
}

// ---------------------------------------------------------------------------
// kernel_launch: s2 runs convertB -> gather (DRAM-bound); main runs
// sniff -> scores -> topk -> convertA -> (wait convertB) -> mma GEMM.
// metadata order: vision_tokens, input_ids, ln_gamma, ln_beta, scorer_w,
//                 scorer_b, proj_w, proj_b, embed_table
// ---------------------------------------------------------------------------
extern "C" void kernel_launch(void* const* d_in, const int* in_sizes, int n_in,
                              void* d_out, int out_size) {
    const float* vision_tokens = (const float*)d_in[0];
    const void*  input_ids     = d_in[1];
    const float* ln_gamma      = (const float*)d_in[2];
    const float* scorer_w      = (const float*)d_in[4];
    const float* proj_w        = (const float*)d_in[6];
    const float* proj_b        = (const float*)d_in[7];
    const float* embed_table   = (const float*)d_in[8];
    float* out = (float*)d_out;

    static cudaStream_t s2 = nullptr;
    static cudaEvent_t eFork = nullptr, eB = nullptr, eJoin = nullptr;
    if (s2 == nullptr) {
        cudaStreamCreateWithFlags(&s2, cudaStreamNonBlocking);
        cudaEventCreateWithFlags(&eFork, cudaEventDisableTiming);
        cudaEventCreateWithFlags(&eB, cudaEventDisableTiming);
        cudaEventCreateWithFlags(&eJoin, cudaEventDisableTiming);
        cudaFuncSetAttribute(gemm_mma_kernel,
                             cudaFuncAttributeMaxDynamicSharedMemorySize, SMEM_TOTAL);
    }

    sniff_kernel<<<1, 32>>>((const int*)input_ids);
    cudaEventRecord(eFork, 0);
    cudaStreamWaitEvent(s2, eFork, 0);

    // stream s2: B conversion, then the big DRAM-bound gather
    {
        dim3 gb(DL / 32, DV / 32);    // 128 x 24
        convertB_kernel<<<gb, 256, 0, s2>>>(proj_w);
    }
    cudaEventRecord(eB, s2);
    gather_kernel<<<B_SZ * T_SZ, 256, 0, s2>>>(input_ids, embed_table, out);
    cudaEventRecord(eJoin, s2);

    // main stream: scoring chain -> GEMM
    scores_kernel<<<(B_SZ * P_SZ * 32 + 255) / 256, 256>>>(vision_tokens, ln_gamma, scorer_w);
    topk_kernel<<<(B_SZ * 32 + 255) / 256, 256>>>();
    convertA_kernel<<<M_TOT, 128>>>(vision_tokens);
    cudaStreamWaitEvent(0, eB, 0);
    gemm_mma_kernel<<<(M_TOT / TM) * (DL / TN), 256, SMEM_TOTAL>>>(proj_b, out);

    cudaStreamWaitEvent(0, eJoin, 0);
}

// round 8
// speedup vs baseline: 2.3573x; 1.0024x over previous
#include <cuda_runtime.h>
#include <cuda_bf16.h>
#include <float.h>
#include <stdint.h>

// ---------------------------------------------------------------------------
// Problem constants (fixed shapes for SparseVLMModel_59725815218738)
// ---------------------------------------------------------------------------
#define B_SZ    64
#define S_SZ    197
#define P_SZ    196
#define T_SZ    512
#define DV      768
#define DL      4096
#define TOPK    32
#define OUT_S   (TOPK + T_SZ)   // 544
#define LN_EPS  1e-5f

#define M_TOT   (B_SZ * TOPK)   // 2048
#define KC      (3 * DV)        // 2304: [Ahi|Ahi|Alo] x [Bhi|Blo|Bhi]
#define TM      128
#define TN      128
#define KCHUNK  64
#define NCHUNK  (KC / KCHUNK)   // 36

// Scratch (no cudaMalloc allowed)
__device__ float g_scores[B_SZ * P_SZ];
__device__ int   g_topk[M_TOT];
__device__ int   g_is64;
__device__ __align__(128) __nv_bfloat16 g_A[(size_t)M_TOT * KC]; // 9.4 MB
__device__ __align__(128) __nv_bfloat16 g_B[(size_t)DL * KC];    // 18.9 MB

__device__ __forceinline__ uint32_t smem_u32(const void* p) {
    uint32_t a;
    asm("{ .reg .u64 t; cvta.to.shared.u64 t, %1; cvt.u32.u64 %0, t; }" : "=r"(a) : "l"(p));
    return a;
}
__device__ __forceinline__ void ldsm4(uint32_t* r, uint32_t addr) {
    asm volatile("ldmatrix.sync.aligned.m8n8.x4.shared.b16 {%0,%1,%2,%3}, [%4];"
                 : "=r"(r[0]), "=r"(r[1]), "=r"(r[2]), "=r"(r[3]) : "r"(addr));
}
__device__ __forceinline__ void mma_bf16(float* c, const uint32_t* a,
                                         uint32_t b0, uint32_t b1) {
    asm volatile(
        "mma.sync.aligned.m16n8k16.row.col.f32.bf16.bf16.f32 "
        "{%0,%1,%2,%3}, {%4,%5,%6,%7}, {%8,%9}, {%0,%1,%2,%3};"
        : "+f"(c[0]), "+f"(c[1]), "+f"(c[2]), "+f"(c[3])
        : "r"(a[0]), "r"(a[1]), "r"(a[2]), "r"(a[3]), "r"(b0), "r"(b1));
}
__device__ __forceinline__ void cp16(uint32_t saddr, const void* g) {
    asm volatile("cp.async.cg.shared.global [%0], [%1], 16;"
                 :: "r"(saddr), "l"(g) : "memory");
}
#define CP_COMMIT() asm volatile("cp.async.commit_group;" ::: "memory")
#define CP_WAIT2()  asm volatile("cp.async.wait_group 2;" ::: "memory")
#define SW128(x) ((x) ^ (((x) >> 3) & 0x70))

// ---------------------------------------------------------------------------
// 0. Sniff int32 vs int64 ids. ids < 32000, so int64 => every odd word == 0.
// ---------------------------------------------------------------------------
__global__ void sniff_kernel(const int* __restrict__ ids) {
    unsigned nz = __ballot_sync(0xffffffffu, ids[2 * threadIdx.x + 1] != 0);
    if (threadIdx.x == 0) g_is64 = (nz == 0u) ? 1 : 0;
}

// ---------------------------------------------------------------------------
// 1. Scores: warp-per-row LayerNorm dot (ordering-equivalent form)
// ---------------------------------------------------------------------------
__global__ void __launch_bounds__(256)
scores_kernel(const float* __restrict__ vt,
              const float* __restrict__ gamma,
              const float* __restrict__ w) {
    int warp = (blockIdx.x * 256 + threadIdx.x) >> 5;
    int lane = threadIdx.x & 31;
    if (warp >= B_SZ * P_SZ) return;
    int b = warp / P_SZ, s = warp % P_SZ;
    const float4* x4 = (const float4*)(vt + (size_t)(b * S_SZ + 1 + s) * DV);
    const float4* g4 = (const float4*)gamma;
    const float4* w4 = (const float4*)w;

    float s1 = 0.f, s2 = 0.f, sgw = 0.f, cgw = 0.f;
    #pragma unroll
    for (int i = 0; i < 6; i++) {
        int idx = lane + i * 32;
        float4 xv = x4[idx];
        float4 gv = g4[idx];
        float4 wv = w4[idx];
        float gw0 = gv.x * wv.x, gw1 = gv.y * wv.y, gw2 = gv.z * wv.z, gw3 = gv.w * wv.w;
        s1 += xv.x + xv.y + xv.z + xv.w;
        s2 += xv.x * xv.x + xv.y * xv.y + xv.z * xv.z + xv.w * xv.w;
        sgw += xv.x * gw0 + xv.y * gw1 + xv.z * gw2 + xv.w * gw3;
        cgw += gw0 + gw1 + gw2 + gw3;
    }
    #pragma unroll
    for (int st = 16; st > 0; st >>= 1) {
        s1  += __shfl_xor_sync(0xffffffffu, s1, st);
        s2  += __shfl_xor_sync(0xffffffffu, s2, st);
        sgw += __shfl_xor_sync(0xffffffffu, sgw, st);
        cgw += __shfl_xor_sync(0xffffffffu, cgw, st);
    }
    if (lane == 0) {
        float mean = s1 * (1.0f / DV);
        float var  = s2 * (1.0f / DV) - mean * mean;
        float rstd = rsqrtf(var + LN_EPS);
        g_scores[warp] = rstd * (sgw - mean * cgw);
    }
}

// ---------------------------------------------------------------------------
// 2. Top-32 per batch: warp-per-batch register argmax, stable ties.
// ---------------------------------------------------------------------------
__global__ void __launch_bounds__(256)
topk_kernel() {
    int warp = (blockIdx.x * 256 + threadIdx.x) >> 5;   // 0..63
    int lane = threadIdx.x & 31;
    if (warp >= B_SZ) return;
    float v[7];
    #pragma unroll
    for (int i = 0; i < 7; i++) {
        int idx = lane + i * 32;
        v[i] = (idx < P_SZ) ? g_scores[warp * P_SZ + idx] : -FLT_MAX;
    }
    for (int k = 0; k < TOPK; k++) {
        float best = -FLT_MAX; int bi = 0;
        #pragma unroll
        for (int i = 0; i < 7; i++)
            if (v[i] > best) { best = v[i]; bi = i; }    // ascending idx: stable
        int bidx = lane + bi * 32;
        #pragma unroll
        for (int st = 16; st > 0; st >>= 1) {
            float ov = __shfl_xor_sync(0xffffffffu, best, st);
            int   oi = __shfl_xor_sync(0xffffffffu, bidx, st);
            if (ov > best || (ov == best && oi < bidx)) { best = ov; bidx = oi; }
        }
        if (lane == 0) g_topk[warp * TOPK + k] = bidx;
        if ((bidx & 31) == lane) v[bidx >> 5] = -FLT_MAX;
    }
}

// ---------------------------------------------------------------------------
// 3a. Convert gathered A rows fp32 -> bf16 split [hi | hi | lo], K = 2304
// ---------------------------------------------------------------------------
__global__ void __launch_bounds__(128)
convertA_kernel(const float* __restrict__ vt) {
    int m = blockIdx.x;                // 0..2047
    int b = m >> 5;
    size_t base = (size_t)(b * S_SZ + 1 + g_topk[m]) * DV;
    __nv_bfloat16* rowA = g_A + (size_t)m * KC;
    int t = threadIdx.x;
    #pragma unroll
    for (int i = 0; i < 3; i++) {
        int p = t + i * 128;           // pair 0..383
        float v0 = vt[base + 2 * p], v1 = vt[base + 2 * p + 1];
        __nv_bfloat16 h0 = __float2bfloat16(v0);
        __nv_bfloat16 h1 = __float2bfloat16(v1);
        __nv_bfloat162 hp; hp.x = h0; hp.y = h1;
        __nv_bfloat162 lp;
        lp.x = __float2bfloat16(v0 - __bfloat162float(h0));
        lp.y = __float2bfloat16(v1 - __bfloat162float(h1));
        *(__nv_bfloat162*)(rowA + 2 * p)          = hp;
        *(__nv_bfloat162*)(rowA + DV + 2 * p)     = hp;
        *(__nv_bfloat162*)(rowA + 2 * DV + 2 * p) = lp;
    }
}

// ---------------------------------------------------------------------------
// 3b. Convert+transpose proj_w [768,4096] -> g_B [4096][hi | lo | hi]
// ---------------------------------------------------------------------------
__global__ void __launch_bounds__(256)
convertB_kernel(const float* __restrict__ W) {
    __shared__ float tile[32][33];
    int n0 = blockIdx.x * 32;          // 128 blocks
    int k0 = blockIdx.y * 32;          // 24 blocks
    int t = threadIdx.x;
    #pragma unroll
    for (int i = 0; i < 4; i++) {
        int e = t + i * 256;
        int r = e >> 5, c = e & 31;
        tile[r][c] = W[(size_t)(k0 + r) * DL + n0 + c];
    }
    __syncthreads();
    #pragma unroll
    for (int i = 0; i < 2; i++) {
        int n = (t >> 4) + i * 16;
        int j = t & 15;
        float v0 = tile[2 * j][n], v1 = tile[2 * j + 1][n];
        __nv_bfloat16 h0 = __float2bfloat16(v0);
        __nv_bfloat16 h1 = __float2bfloat16(v1);
        __nv_bfloat162 hp; hp.x = h0; hp.y = h1;
        __nv_bfloat162 lp;
        lp.x = __float2bfloat16(v0 - __bfloat162float(h0));
        lp.y = __float2bfloat16(v1 - __bfloat162float(h1));
        __nv_bfloat16* rowB = g_B + (size_t)(n0 + n) * KC + k0 + 2 * j;
        *(__nv_bfloat162*)(rowB)          = hp;
        *(__nv_bfloat162*)(rowB + DV)     = lp;
        *(__nv_bfloat162*)(rowB + 2 * DV) = hp;
    }
}

// ---------------------------------------------------------------------------
// 4. mma.sync GEMM: D[2048,4096] = A'[2048,2304] @ B'[4096,2304]^T + bias
//    128x128 tile/CTA, 8 warps x (64x32), KCHUNK=64, SW128 smem,
//    3-stage cp.async pipeline, 2 CTAs/SM.
// ---------------------------------------------------------------------------
#define STAGE_BYTES 32768
#define SA_OFF(st) ((st) * STAGE_BYTES)
#define SB_OFF(st) ((st) * STAGE_BYTES + 16384)
#define SMEM_TOTAL (3 * STAGE_BYTES)    // 96 KB

__global__ void __launch_bounds__(256, 2)
gemm_mma_kernel(const float* __restrict__ bias, float* __restrict__ out) {
    extern __shared__ __align__(1024) char smem[];
    uint32_t sbase = smem_u32(smem);
    int tid = threadIdx.x;
    int wid = tid >> 5, lane = tid & 31;
    int mblk = blockIdx.x >> 5;          // 16
    int nblk = blockIdx.x & 31;          // 32
    int m0 = mblk * TM, n0 = nblk * TN;
    int wm = (wid & 1) * 64;             // warp M offset
    int wn = (wid >> 1) * 32;            // warp N offset

    const __nv_bfloat16* Abase = g_A + (size_t)m0 * KC;
    const __nv_bfloat16* Bbase = g_B + (size_t)n0 * KC;

    // per-thread load coords: 4 x 16B for A, 4 x 16B for B per stage
    int lrow = tid >> 1;                 // 0..127 (two threads per row)
    int ljA  = (tid & 1) * 4;            // 16B unit 0..7 -> here 0 or 4
    // each thread does rows {lrow} with 4 consecutive 16B units
    // covered below with explicit loop

    // ldmatrix lane addressing
    int q = lane >> 3, r8 = lane & 7;
    int qm = (q & 1) * 8;
    int qk = (q >> 1) * 16;

    float acc[4][4][4];
    #pragma unroll
    for (int a = 0; a < 4; a++)
        #pragma unroll
        for (int b = 0; b < 4; b++)
            #pragma unroll
            for (int c = 0; c < 4; c++) acc[a][b][c] = 0.f;

    #define ISSUE(cc) do { \
        int _stg = (cc) % 3; \
        const __nv_bfloat16* Ap = Abase + (size_t)(cc) * KCHUNK; \
        const __nv_bfloat16* Bp = Bbase + (size_t)(cc) * KCHUNK; \
        _Pragma("unroll") \
        for (int i = 0; i < 4; i++) { \
            int f = tid + i * 256; \
            int row = f >> 3, j = f & 7; \
            int off = SW128(row * 128 + j * 16); \
            cp16(sbase + SA_OFF(_stg) + off, Ap + (size_t)row * KC + j * 8); \
            cp16(sbase + SB_OFF(_stg) + off, Bp + (size_t)row * KC + j * 8); \
        } \
    } while (0)

    ISSUE(0); CP_COMMIT();
    ISSUE(1); CP_COMMIT();

    #pragma unroll 1
    for (int c = 0; c < NCHUNK; c++) {
        // issue stage c+2 into buffer (c+2)%3 == (c-1)%3 (reads finished at
        // the end-of-compute sync of iteration c-1)
        if (c + 2 < NCHUNK) ISSUE(c + 2);
        CP_COMMIT();
        CP_WAIT2();                      // stage c's group complete
        __syncthreads();                 // visible to all warps

        int st = c % 3;
        uint32_t abuf = sbase + SA_OFF(st);
        uint32_t bbuf = sbase + SB_OFF(st);
        #pragma unroll
        for (int ks = 0; ks < 4; ks++) {
            uint32_t afr[4][4], bfr[2][4];
            #pragma unroll
            for (int mt = 0; mt < 4; mt++)
                ldsm4(afr[mt], abuf + SW128((wm + mt * 16 + qm + r8) * 128 + ks * 32 + qk));
            #pragma unroll
            for (int nt = 0; nt < 2; nt++)
                ldsm4(bfr[nt], bbuf + SW128((wn + nt * 16 + qm + r8) * 128 + ks * 32 + qk));
            #pragma unroll
            for (int mt = 0; mt < 4; mt++)
                #pragma unroll
                for (int nf = 0; nf < 4; nf++) {
                    int nt = nf >> 1, half = nf & 1;
                    mma_bf16(acc[mt][nf], afr[mt], bfr[nt][half], bfr[nt][half + 2]);
                }
        }
        __syncthreads();                 // all reads of buf st done
    }

    // epilogue: C frag m16n8: c0,c1=(row g, col 2i,2i+1); c2,c3=(row g+8)
    int g = lane >> 2, i2 = (lane & 3) * 2;
    #pragma unroll
    for (int mt = 0; mt < 4; mt++) {
        #pragma unroll
        for (int rh = 0; rh < 2; rh++) {
            int m = m0 + wm + mt * 16 + rh * 8 + g;
            int b = m >> 5, kk = m & 31;
            float* orow = out + (size_t)(b * OUT_S + kk) * DL + n0 + wn;
            #pragma unroll
            for (int nf = 0; nf < 4; nf++) {
                int n = nf * 8 + i2;
                float2 bb = *(const float2*)(bias + n0 + wn + n);
                float2 o;
                o.x = acc[mt][nf][rh * 2 + 0] + bb.x;
                o.y = acc[mt][nf][rh * 2 + 1] + bb.y;
                *(float2*)(orow + n) = o;
            }
        }
    }
    (void)lrow; (void)ljA;
}

// ---------------------------------------------------------------------------
// 5. Embedding gather: streaming loads/stores (no reuse; keep L2 for GEMM)
// ---------------------------------------------------------------------------
__global__ void __launch_bounds__(256)
gather_kernel(const void* __restrict__ ids_raw,
              const float* __restrict__ table,
              float* __restrict__ out) {
    int r = blockIdx.x;               // 0..32767
    int b = r >> 9, t = r & 511;
    long long id;
    if (g_is64) id = ((const long long*)ids_raw)[r];
    else        id = (long long)((const int*)ids_raw)[r];

    const float4* src = (const float4*)(table + (size_t)id * DL);
    float4* dst = (float4*)(out + (size_t)(b * OUT_S + TOPK + t) * DL);
    int tid = threadIdx.x;
    float4 v0 = __ldcs(src + tid);
    float4 v1 = __ldcs(src + tid + 256);
    float4 v2 = __ldcs(src + tid + 512);
    float4 v3 = __ldcs(src + tid + 768);
    __stcs(dst + tid,       v0);
    __stcs(dst + tid + 256, v1);
    __stcs(dst + tid + 512, v2);
    __stcs(dst + tid + 768, v3);
}

// ---------------------------------------------------------------------------
// kernel_launch: s2 = gather (starts right after sniff), s3 = convertB,
// main = scores -> topk -> convA -> (wait convertB) -> cp.async mma GEMM.
// metadata order: vision_tokens, input_ids, ln_gamma, ln_beta, scorer_w,
//                 scorer_b, proj_w, proj_b, embed_table
// ---------------------------------------------------------------------------
extern "C" void kernel_launch(void* const* d_in, const int* in_sizes, int n_in,
                              void* d_out, int out_size) {
    const float* vision_tokens = (const float*)d_in[0];
    const void*  input_ids     = d_in[1];
    const float* ln_gamma      = (const float*)d_in[2];
    const float* scorer_w      = (const float*)d_in[4];
    const float* proj_w        = (const float*)d_in[6];
    const float* proj_b        = (const float*)d_in[7];
    const float* embed_table   = (const float*)d_in[8];
    float* out = (float*)d_out;

    static cudaStream_t s2 = nullptr, s3 = nullptr;
    static cudaEvent_t eFork = nullptr, eB = nullptr, eG = nullptr;
    if (s2 == nullptr) {
        cudaStreamCreateWithFlags(&s2, cudaStreamNonBlocking);
        cudaStreamCreateWithFlags(&s3, cudaStreamNonBlocking);
        cudaEventCreateWithFlags(&eFork, cudaEventDisableTiming);
        cudaEventCreateWithFlags(&eB, cudaEventDisableTiming);
        cudaEventCreateWithFlags(&eG, cudaEventDisableTiming);
        cudaFuncSetAttribute(gemm_mma_kernel,
                             cudaFuncAttributeMaxDynamicSharedMemorySize, SMEM_TOTAL);
    }

    sniff_kernel<<<1, 32>>>((const int*)input_ids);
    cudaEventRecord(eFork, 0);
    cudaStreamWaitEvent(s2, eFork, 0);
    cudaStreamWaitEvent(s3, eFork, 0);

    // stream s2: the big DRAM-bound gather, starting immediately
    gather_kernel<<<B_SZ * T_SZ, 256, 0, s2>>>(input_ids, embed_table, out);
    cudaEventRecord(eG, s2);

    // stream s3: B conversion for the GEMM
    {
        dim3 gb(DL / 32, DV / 32);    // 128 x 24
        convertB_kernel<<<gb, 256, 0, s3>>>(proj_w);
    }
    cudaEventRecord(eB, s3);

    // main stream: scoring chain -> GEMM
    scores_kernel<<<(B_SZ * P_SZ * 32 + 255) / 256, 256>>>(vision_tokens, ln_gamma, scorer_w);
    topk_kernel<<<(B_SZ * 32 + 255) / 256, 256>>>();
    convertA_kernel<<<M_TOT, 128>>>(vision_tokens);
    cudaStreamWaitEvent(0, eB, 0);
    gemm_mma_kernel<<<(M_TOT / TM) * (DL / TN), 256, SMEM_TOTAL>>>(proj_b, out);

    cudaStreamWaitEvent(0, eG, 0);
}

// round 9
// speedup vs baseline: 2.7146x; 1.1516x over previous
#include <cuda_runtime.h>
#include <cuda_fp16.h>
#include <float.h>
#include <stdint.h>

// ---------------------------------------------------------------------------
// Problem constants (fixed shapes for SparseVLMModel_59725815218738)
// ---------------------------------------------------------------------------
#define B_SZ    64
#define S_SZ    197
#define P_SZ    196
#define T_SZ    512
#define DV      768
#define DL      4096
#define TOPK    32
#define OUT_S   (TOPK + T_SZ)   // 544
#define LN_EPS  1e-5f

#define M_TOT   (B_SZ * TOPK)   // 2048
#define KC      (2 * DV)        // 1536: A'=[Ahi|Ahi], B'=[Bhi|Blo] (fp16 2-term)
#define TM      128
#define TN      128
#define KCHUNK  64
#define NCHUNK  (KC / KCHUNK)   // 24

// Scratch (no cudaMalloc allowed)
__device__ float g_scores[B_SZ * P_SZ];
__device__ int   g_topk[M_TOT];
__device__ int   g_is64;
__device__ __align__(128) __half g_A[(size_t)M_TOT * KC]; // 6.3 MB
__device__ __align__(128) __half g_B[(size_t)DL * KC];    // 12.6 MB

__device__ __forceinline__ uint32_t smem_u32(const void* p) {
    uint32_t a;
    asm("{ .reg .u64 t; cvta.to.shared.u64 t, %1; cvt.u32.u64 %0, t; }" : "=r"(a) : "l"(p));
    return a;
}
__device__ __forceinline__ void ldsm4(uint32_t* r, uint32_t addr) {
    asm volatile("ldmatrix.sync.aligned.m8n8.x4.shared.b16 {%0,%1,%2,%3}, [%4];"
                 : "=r"(r[0]), "=r"(r[1]), "=r"(r[2]), "=r"(r[3]) : "r"(addr));
}
__device__ __forceinline__ void mma_f16(float* c, const uint32_t* a,
                                        uint32_t b0, uint32_t b1) {
    asm volatile(
        "mma.sync.aligned.m16n8k16.row.col.f32.f16.f16.f32 "
        "{%0,%1,%2,%3}, {%4,%5,%6,%7}, {%8,%9}, {%0,%1,%2,%3};"
        : "+f"(c[0]), "+f"(c[1]), "+f"(c[2]), "+f"(c[3])
        : "r"(a[0]), "r"(a[1]), "r"(a[2]), "r"(a[3]), "r"(b0), "r"(b1));
}
__device__ __forceinline__ void cp16(uint32_t saddr, const void* g) {
    asm volatile("cp.async.cg.shared.global [%0], [%1], 16;"
                 :: "r"(saddr), "l"(g) : "memory");
}
#define CP_COMMIT() asm volatile("cp.async.commit_group;" ::: "memory")
#define CP_WAIT2()  asm volatile("cp.async.wait_group 2;" ::: "memory")
#define SW128(x) ((x) ^ (((x) >> 3) & 0x70))

// ---------------------------------------------------------------------------
// 0. Sniff int32 vs int64 ids. ids < 32000, so int64 => every odd word == 0.
// ---------------------------------------------------------------------------
__global__ void sniff_kernel(const int* __restrict__ ids) {
    unsigned nz = __ballot_sync(0xffffffffu, ids[2 * threadIdx.x + 1] != 0);
    if (threadIdx.x == 0) g_is64 = (nz == 0u) ? 1 : 0;
}

// ---------------------------------------------------------------------------
// 1. Scores: warp-per-row LayerNorm dot (ordering-equivalent form)
// ---------------------------------------------------------------------------
__global__ void __launch_bounds__(256)
scores_kernel(const float* __restrict__ vt,
              const float* __restrict__ gamma,
              const float* __restrict__ w) {
    int warp = (blockIdx.x * 256 + threadIdx.x) >> 5;
    int lane = threadIdx.x & 31;
    if (warp >= B_SZ * P_SZ) return;
    int b = warp / P_SZ, s = warp % P_SZ;
    const float4* x4 = (const float4*)(vt + (size_t)(b * S_SZ + 1 + s) * DV);
    const float4* g4 = (const float4*)gamma;
    const float4* w4 = (const float4*)w;

    float s1 = 0.f, s2 = 0.f, sgw = 0.f, cgw = 0.f;
    #pragma unroll
    for (int i = 0; i < 6; i++) {
        int idx = lane + i * 32;
        float4 xv = x4[idx];
        float4 gv = g4[idx];
        float4 wv = w4[idx];
        float gw0 = gv.x * wv.x, gw1 = gv.y * wv.y, gw2 = gv.z * wv.z, gw3 = gv.w * wv.w;
        s1 += xv.x + xv.y + xv.z + xv.w;
        s2 += xv.x * xv.x + xv.y * xv.y + xv.z * xv.z + xv.w * xv.w;
        sgw += xv.x * gw0 + xv.y * gw1 + xv.z * gw2 + xv.w * gw3;
        cgw += gw0 + gw1 + gw2 + gw3;
    }
    #pragma unroll
    for (int st = 16; st > 0; st >>= 1) {
        s1  += __shfl_xor_sync(0xffffffffu, s1, st);
        s2  += __shfl_xor_sync(0xffffffffu, s2, st);
        sgw += __shfl_xor_sync(0xffffffffu, sgw, st);
        cgw += __shfl_xor_sync(0xffffffffu, cgw, st);
    }
    if (lane == 0) {
        float mean = s1 * (1.0f / DV);
        float var  = s2 * (1.0f / DV) - mean * mean;
        float rstd = rsqrtf(var + LN_EPS);
        g_scores[warp] = rstd * (sgw - mean * cgw);
    }
}

// ---------------------------------------------------------------------------
// 2. Top-32 per batch: warp-per-batch register argmax, stable ties.
// ---------------------------------------------------------------------------
__global__ void __launch_bounds__(256)
topk_kernel() {
    int warp = (blockIdx.x * 256 + threadIdx.x) >> 5;   // 0..63
    int lane = threadIdx.x & 31;
    if (warp >= B_SZ) return;
    float v[7];
    #pragma unroll
    for (int i = 0; i < 7; i++) {
        int idx = lane + i * 32;
        v[i] = (idx < P_SZ) ? g_scores[warp * P_SZ + idx] : -FLT_MAX;
    }
    for (int k = 0; k < TOPK; k++) {
        float best = -FLT_MAX; int bi = 0;
        #pragma unroll
        for (int i = 0; i < 7; i++)
            if (v[i] > best) { best = v[i]; bi = i; }    // ascending idx: stable
        int bidx = lane + bi * 32;
        #pragma unroll
        for (int st = 16; st > 0; st >>= 1) {
            float ov = __shfl_xor_sync(0xffffffffu, best, st);
            int   oi = __shfl_xor_sync(0xffffffffu, bidx, st);
            if (ov > best || (ov == best && oi < bidx)) { best = ov; bidx = oi; }
        }
        if (lane == 0) g_topk[warp * TOPK + k] = bidx;
        if ((bidx & 31) == lane) v[bidx >> 5] = -FLT_MAX;
    }
}

// ---------------------------------------------------------------------------
// 3a. Convert gathered A rows fp32 -> fp16 hi, duplicated: [hi | hi]
// ---------------------------------------------------------------------------
__global__ void __launch_bounds__(128)
convertA_kernel(const float* __restrict__ vt) {
    int m = blockIdx.x;                // 0..2047
    int b = m >> 5;
    size_t base = (size_t)(b * S_SZ + 1 + g_topk[m]) * DV;
    __half* rowA = g_A + (size_t)m * KC;
    int t = threadIdx.x;
    #pragma unroll
    for (int i = 0; i < 3; i++) {
        int p = t + i * 128;           // pair 0..383
        float v0 = vt[base + 2 * p], v1 = vt[base + 2 * p + 1];
        __half2 hp;
        hp.x = __float2half_rn(v0);
        hp.y = __float2half_rn(v1);
        *(__half2*)(rowA + 2 * p)      = hp;
        *(__half2*)(rowA + DV + 2 * p) = hp;
    }
}

// ---------------------------------------------------------------------------
// 3b. Convert+transpose proj_w [768,4096] -> g_B [4096][Bhi | Blo]
// ---------------------------------------------------------------------------
__global__ void __launch_bounds__(256)
convertB_kernel(const float* __restrict__ W) {
    __shared__ float tile[32][33];
    int n0 = blockIdx.x * 32;          // 128 blocks
    int k0 = blockIdx.y * 32;          // 24 blocks
    int t = threadIdx.x;
    #pragma unroll
    for (int i = 0; i < 4; i++) {
        int e = t + i * 256;
        int r = e >> 5, c = e & 31;
        tile[r][c] = W[(size_t)(k0 + r) * DL + n0 + c];
    }
    __syncthreads();
    #pragma unroll
    for (int i = 0; i < 2; i++) {
        int n = (t >> 4) + i * 16;
        int j = t & 15;
        float v0 = tile[2 * j][n], v1 = tile[2 * j + 1][n];
        __half h0 = __float2half_rn(v0);
        __half h1 = __float2half_rn(v1);
        __half2 hp; hp.x = h0; hp.y = h1;
        __half2 lp;
        lp.x = __float2half_rn(v0 - __half2float(h0));
        lp.y = __float2half_rn(v1 - __half2float(h1));
        __half* rowB = g_B + (size_t)(n0 + n) * KC + k0 + 2 * j;
        *(__half2*)(rowB)      = hp;
        *(__half2*)(rowB + DV) = lp;
    }
}

// ---------------------------------------------------------------------------
// 4. mma.sync GEMM: D[2048,4096] = A'[2048,1536] @ B'[4096,1536]^T + bias
//    128x128 tile/CTA, 8 warps x (64x32), KCHUNK=64, SW128 smem,
//    3-stage cp.async pipeline, 2 CTAs/SM, CTA-swizzled for L2 locality.
// ---------------------------------------------------------------------------
#define STAGE_BYTES 32768
#define SA_OFF(st) ((st) * STAGE_BYTES)
#define SB_OFF(st) ((st) * STAGE_BYTES + 16384)
#define SMEM_TOTAL (3 * STAGE_BYTES)    // 96 KB

__global__ void __launch_bounds__(256, 2)
gemm_mma_kernel(const float* __restrict__ bias, float* __restrict__ out) {
    extern __shared__ __align__(1024) char smem[];
    uint32_t sbase = smem_u32(smem);
    int tid = threadIdx.x;
    int wid = tid >> 5, lane = tid & 31;
    // swizzle: mblk inner -> 296 concurrent CTAs share all of A + ~18 B tiles
    int mblk = blockIdx.x & 15;          // 16
    int nblk = blockIdx.x >> 4;          // 32
    int m0 = mblk * TM, n0 = nblk * TN;
    int wm = (wid & 1) * 64;             // warp M offset
    int wn = (wid >> 1) * 32;            // warp N offset

    const __half* Abase = g_A + (size_t)m0 * KC;
    const __half* Bbase = g_B + (size_t)n0 * KC;

    // ldmatrix lane addressing
    int q = lane >> 3, r8 = lane & 7;
    int qm = (q & 1) * 8;
    int qk = (q >> 1) * 16;

    float acc[4][4][4];
    #pragma unroll
    for (int a = 0; a < 4; a++)
        #pragma unroll
        for (int b = 0; b < 4; b++)
            #pragma unroll
            for (int c = 0; c < 4; c++) acc[a][b][c] = 0.f;

    #define ISSUE(cc) do { \
        int _stg = (cc) % 3; \
        const __half* Ap = Abase + (size_t)(cc) * KCHUNK; \
        const __half* Bp = Bbase + (size_t)(cc) * KCHUNK; \
        _Pragma("unroll") \
        for (int i = 0; i < 4; i++) { \
            int f = tid + i * 256; \
            int row = f >> 3, j = f & 7; \
            int off = SW128(row * 128 + j * 16); \
            cp16(sbase + SA_OFF(_stg) + off, Ap + (size_t)row * KC + j * 8); \
            cp16(sbase + SB_OFF(_stg) + off, Bp + (size_t)row * KC + j * 8); \
        } \
    } while (0)

    ISSUE(0); CP_COMMIT();
    ISSUE(1); CP_COMMIT();

    #pragma unroll 1
    for (int c = 0; c < NCHUNK; c++) {
        if (c + 2 < NCHUNK) ISSUE(c + 2);
        CP_COMMIT();
        CP_WAIT2();                      // stage c's group complete
        __syncthreads();

        int st = c % 3;
        uint32_t abuf = sbase + SA_OFF(st);
        uint32_t bbuf = sbase + SB_OFF(st);
        #pragma unroll
        for (int ks = 0; ks < 4; ks++) {
            uint32_t afr[4][4], bfr[2][4];
            #pragma unroll
            for (int mt = 0; mt < 4; mt++)
                ldsm4(afr[mt], abuf + SW128((wm + mt * 16 + qm + r8) * 128 + ks * 32 + qk));
            #pragma unroll
            for (int nt = 0; nt < 2; nt++)
                ldsm4(bfr[nt], bbuf + SW128((wn + nt * 16 + qm + r8) * 128 + ks * 32 + qk));
            #pragma unroll
            for (int mt = 0; mt < 4; mt++)
                #pragma unroll
                for (int nf = 0; nf < 4; nf++) {
                    int nt = nf >> 1, half = nf & 1;
                    mma_f16(acc[mt][nf], afr[mt], bfr[nt][half], bfr[nt][half + 2]);
                }
        }
        __syncthreads();                 // all reads of buf st done
    }

    // epilogue: C frag m16n8: c0,c1=(row g, col 2i,2i+1); c2,c3=(row g+8)
    int g = lane >> 2, i2 = (lane & 3) * 2;
    #pragma unroll
    for (int mt = 0; mt < 4; mt++) {
        #pragma unroll
        for (int rh = 0; rh < 2; rh++) {
            int m = m0 + wm + mt * 16 + rh * 8 + g;
            int b = m >> 5, kk = m & 31;
            float* orow = out + (size_t)(b * OUT_S + kk) * DL + n0 + wn;
            #pragma unroll
            for (int nf = 0; nf < 4; nf++) {
                int n = nf * 8 + i2;
                float2 bb = *(const float2*)(bias + n0 + wn + n);
                float2 o;
                o.x = acc[mt][nf][rh * 2 + 0] + bb.x;
                o.y = acc[mt][nf][rh * 2 + 1] + bb.y;
                *(float2*)(orow + n) = o;
            }
        }
    }
}

// ---------------------------------------------------------------------------
// 5. Embedding gather: persistent grid-stride copy, streaming hints.
// ---------------------------------------------------------------------------
#define GATHER_BLOCKS 1184   // 148 SMs x 8 resident blocks
__global__ void __launch_bounds__(256)
gather_kernel(const void* __restrict__ ids_raw,
              const float* __restrict__ table,
              float* __restrict__ out) {
    int tid = threadIdx.x;
    int is64 = g_is64;
    for (int r = blockIdx.x; r < B_SZ * T_SZ; r += GATHER_BLOCKS) {
        int b = r >> 9, t = r & 511;
        long long id;
        if (is64) id = ((const long long*)ids_raw)[r];
        else      id = (long long)((const int*)ids_raw)[r];

        const float4* src = (const float4*)(table + (size_t)id * DL);
        float4* dst = (float4*)(out + (size_t)(b * OUT_S + TOPK + t) * DL);
        float4 v0 = __ldcs(src + tid);
        float4 v1 = __ldcs(src + tid + 256);
        float4 v2 = __ldcs(src + tid + 512);
        float4 v3 = __ldcs(src + tid + 768);
        __stcs(dst + tid,       v0);
        __stcs(dst + tid + 256, v1);
        __stcs(dst + tid + 512, v2);
        __stcs(dst + tid + 768, v3);
    }
}

// ---------------------------------------------------------------------------
// kernel_launch: s2 = gather (starts right after sniff), s3 = convertB,
// main = scores -> topk -> convA -> (wait convertB) -> cp.async mma GEMM.
// metadata order: vision_tokens, input_ids, ln_gamma, ln_beta, scorer_w,
//                 scorer_b, proj_w, proj_b, embed_table
// ---------------------------------------------------------------------------
extern "C" void kernel_launch(void* const* d_in, const int* in_sizes, int n_in,
                              void* d_out, int out_size) {
    const float* vision_tokens = (const float*)d_in[0];
    const void*  input_ids     = d_in[1];
    const float* ln_gamma      = (const float*)d_in[2];
    const float* scorer_w      = (const float*)d_in[4];
    const float* proj_w        = (const float*)d_in[6];
    const float* proj_b        = (const float*)d_in[7];
    const float* embed_table   = (const float*)d_in[8];
    float* out = (float*)d_out;

    static cudaStream_t s2 = nullptr, s3 = nullptr;
    static cudaEvent_t eFork = nullptr, eB = nullptr, eG = nullptr;
    if (s2 == nullptr) {
        cudaStreamCreateWithFlags(&s2, cudaStreamNonBlocking);
        cudaStreamCreateWithFlags(&s3, cudaStreamNonBlocking);
        cudaEventCreateWithFlags(&eFork, cudaEventDisableTiming);
        cudaEventCreateWithFlags(&eB, cudaEventDisableTiming);
        cudaEventCreateWithFlags(&eG, cudaEventDisableTiming);
        cudaFuncSetAttribute(gemm_mma_kernel,
                             cudaFuncAttributeMaxDynamicSharedMemorySize, SMEM_TOTAL);
    }

    sniff_kernel<<<1, 32>>>((const int*)input_ids);
    cudaEventRecord(eFork, 0);
    cudaStreamWaitEvent(s2, eFork, 0);
    cudaStreamWaitEvent(s3, eFork, 0);

    // stream s2: the big DRAM-bound gather, starting immediately
    gather_kernel<<<GATHER_BLOCKS, 256, 0, s2>>>(input_ids, embed_table, out);
    cudaEventRecord(eG, s2);

    // stream s3: B conversion for the GEMM
    {
        dim3 gb(DL / 32, DV / 32);    // 128 x 24
        convertB_kernel<<<gb, 256, 0, s3>>>(proj_w);
    }
    cudaEventRecord(eB, s3);

    // main stream: scoring chain -> GEMM
    scores_kernel<<<(B_SZ * P_SZ * 32 + 255) / 256, 256>>>(vision_tokens, ln_gamma, scorer_w);
    topk_kernel<<<(B_SZ * 32 + 255) / 256, 256>>>();
    convertA_kernel<<<M_TOT, 128>>>(vision_tokens);
    cudaStreamWaitEvent(0, eB, 0);
    gemm_mma_kernel<<<(M_TOT / TM) * (DL / TN), 256, SMEM_TOTAL>>>(proj_b, out);

    cudaStreamWaitEvent(0, eG, 0);
}

// round 10
// speedup vs baseline: 2.8312x; 1.0429x over previous
#include <cuda_runtime.h>
#include <cuda_fp16.h>
#include <float.h>
#include <stdint.h>

// ---------------------------------------------------------------------------
// Problem constants (fixed shapes for SparseVLMModel_59725815218738)
// ---------------------------------------------------------------------------
#define B_SZ    64
#define S_SZ    197
#define P_SZ    196
#define T_SZ    512
#define DV      768
#define DL      4096
#define TOPK    32
#define OUT_S   (TOPK + T_SZ)   // 544
#define LN_EPS  1e-5f

#define M_TOT   (B_SZ * TOPK)   // 2048
#define KC      (2 * DV)        // 1536: A'=[Ahi|Ahi], B'=[Bhi|Blo] (fp16 2-term)
#define TM      128
#define TN      128
#define KCHUNK  64
#define NCHUNK  (KC / KCHUNK)   // 24

// Scratch (no cudaMalloc allowed)
__device__ float g_scores[B_SZ * P_SZ];
__device__ int   g_topk[M_TOT];
__device__ int   g_is64;
__device__ __align__(128) __half g_A[(size_t)M_TOT * KC]; // 6.3 MB
__device__ __align__(128) __half g_B[(size_t)DL * KC];    // 12.6 MB

__device__ __forceinline__ uint32_t smem_u32(const void* p) {
    uint32_t a;
    asm("{ .reg .u64 t; cvta.to.shared.u64 t, %1; cvt.u32.u64 %0, t; }" : "=r"(a) : "l"(p));
    return a;
}
__device__ __forceinline__ void ldsm4(uint32_t* r, uint32_t addr) {
    asm volatile("ldmatrix.sync.aligned.m8n8.x4.shared.b16 {%0,%1,%2,%3}, [%4];"
                 : "=r"(r[0]), "=r"(r[1]), "=r"(r[2]), "=r"(r[3]) : "r"(addr));
}
__device__ __forceinline__ void mma_f16(float* c, const uint32_t* a,
                                        uint32_t b0, uint32_t b1) {
    asm volatile(
        "mma.sync.aligned.m16n8k16.row.col.f32.f16.f16.f32 "
        "{%0,%1,%2,%3}, {%4,%5,%6,%7}, {%8,%9}, {%0,%1,%2,%3};"
        : "+f"(c[0]), "+f"(c[1]), "+f"(c[2]), "+f"(c[3])
        : "r"(a[0]), "r"(a[1]), "r"(a[2]), "r"(a[3]), "r"(b0), "r"(b1));
}
__device__ __forceinline__ void cp16(uint32_t saddr, const void* g) {
    asm volatile("cp.async.cg.shared.global [%0], [%1], 16;"
                 :: "r"(saddr), "l"(g) : "memory");
}
#define CP_COMMIT() asm volatile("cp.async.commit_group;" ::: "memory")
#define CP_WAIT2()  asm volatile("cp.async.wait_group 2;" ::: "memory")
#define SW128(x) ((x) ^ (((x) >> 3) & 0x70))

// ---------------------------------------------------------------------------
// 1. Scores: warp-per-row LayerNorm dot (ordering-equivalent form)
// ---------------------------------------------------------------------------
__global__ void __launch_bounds__(256)
scores_kernel(const float* __restrict__ vt,
              const float* __restrict__ gamma,
              const float* __restrict__ w) {
    int warp = (blockIdx.x * 256 + threadIdx.x) >> 5;
    int lane = threadIdx.x & 31;
    if (warp >= B_SZ * P_SZ) return;
    int b = warp / P_SZ, s = warp % P_SZ;
    const float4* x4 = (const float4*)(vt + (size_t)(b * S_SZ + 1 + s) * DV);
    const float4* g4 = (const float4*)gamma;
    const float4* w4 = (const float4*)w;

    float s1 = 0.f, s2 = 0.f, sgw = 0.f, cgw = 0.f;
    #pragma unroll
    for (int i = 0; i < 6; i++) {
        int idx = lane + i * 32;
        float4 xv = x4[idx];
        float4 gv = g4[idx];
        float4 wv = w4[idx];
        float gw0 = gv.x * wv.x, gw1 = gv.y * wv.y, gw2 = gv.z * wv.z, gw3 = gv.w * wv.w;
        s1 += xv.x + xv.y + xv.z + xv.w;
        s2 += xv.x * xv.x + xv.y * xv.y + xv.z * xv.z + xv.w * xv.w;
        sgw += xv.x * gw0 + xv.y * gw1 + xv.z * gw2 + xv.w * gw3;
        cgw += gw0 + gw1 + gw2 + gw3;
    }
    #pragma unroll
    for (int st = 16; st > 0; st >>= 1) {
        s1  += __shfl_xor_sync(0xffffffffu, s1, st);
        s2  += __shfl_xor_sync(0xffffffffu, s2, st);
        sgw += __shfl_xor_sync(0xffffffffu, sgw, st);
        cgw += __shfl_xor_sync(0xffffffffu, cgw, st);
    }
    if (lane == 0) {
        float mean = s1 * (1.0f / DV);
        float var  = s2 * (1.0f / DV) - mean * mean;
        float rstd = rsqrtf(var + LN_EPS);
        g_scores[warp] = rstd * (sgw - mean * cgw);
    }
}

// ---------------------------------------------------------------------------
// 2. Top-32 per batch: warp-per-batch register argmax, stable ties.
// ---------------------------------------------------------------------------
__global__ void __launch_bounds__(256)
topk_kernel() {
    int warp = (blockIdx.x * 256 + threadIdx.x) >> 5;   // 0..63
    int lane = threadIdx.x & 31;
    if (warp >= B_SZ) return;
    float v[7];
    #pragma unroll
    for (int i = 0; i < 7; i++) {
        int idx = lane + i * 32;
        v[i] = (idx < P_SZ) ? g_scores[warp * P_SZ + idx] : -FLT_MAX;
    }
    for (int k = 0; k < TOPK; k++) {
        float best = -FLT_MAX; int bi = 0;
        #pragma unroll
        for (int i = 0; i < 7; i++)
            if (v[i] > best) { best = v[i]; bi = i; }    // ascending idx: stable
        int bidx = lane + bi * 32;
        #pragma unroll
        for (int st = 16; st > 0; st >>= 1) {
            float ov = __shfl_xor_sync(0xffffffffu, best, st);
            int   oi = __shfl_xor_sync(0xffffffffu, bidx, st);
            if (ov > best || (ov == best && oi < bidx)) { best = ov; bidx = oi; }
        }
        if (lane == 0) g_topk[warp * TOPK + k] = bidx;
        if ((bidx & 31) == lane) v[bidx >> 5] = -FLT_MAX;
    }
}

// ---------------------------------------------------------------------------
// 3a. Convert gathered A rows fp32 -> fp16 hi, duplicated: [hi | hi]
// ---------------------------------------------------------------------------
__global__ void __launch_bounds__(128)
convertA_kernel(const float* __restrict__ vt) {
    int m = blockIdx.x;                // 0..2047
    int b = m >> 5;
    size_t base = (size_t)(b * S_SZ + 1 + g_topk[m]) * DV;
    __half* rowA = g_A + (size_t)m * KC;
    int t = threadIdx.x;
    #pragma unroll
    for (int i = 0; i < 3; i++) {
        int p = t + i * 128;           // pair 0..383
        float v0 = vt[base + 2 * p], v1 = vt[base + 2 * p + 1];
        __half2 hp;
        hp.x = __float2half_rn(v0);
        hp.y = __float2half_rn(v1);
        *(__half2*)(rowA + 2 * p)      = hp;
        *(__half2*)(rowA + DV + 2 * p) = hp;
    }
}

// ---------------------------------------------------------------------------
// 3b. Convert+transpose proj_w [768,4096] -> g_B [4096][Bhi | Blo]
// ---------------------------------------------------------------------------
__global__ void __launch_bounds__(256)
convertB_kernel(const float* __restrict__ W) {
    __shared__ float tile[32][33];
    int n0 = blockIdx.x * 32;          // 128 blocks
    int k0 = blockIdx.y * 32;          // 24 blocks
    int t = threadIdx.x;
    #pragma unroll
    for (int i = 0; i < 4; i++) {
        int e = t + i * 256;
        int r = e >> 5, c = e & 31;
        tile[r][c] = W[(size_t)(k0 + r) * DL + n0 + c];
    }
    __syncthreads();
    #pragma unroll
    for (int i = 0; i < 2; i++) {
        int n = (t >> 4) + i * 16;
        int j = t & 15;
        float v0 = tile[2 * j][n], v1 = tile[2 * j + 1][n];
        __half h0 = __float2half_rn(v0);
        __half h1 = __float2half_rn(v1);
        __half2 hp; hp.x = h0; hp.y = h1;
        __half2 lp;
        lp.x = __float2half_rn(v0 - __half2float(h0));
        lp.y = __float2half_rn(v1 - __half2float(h1));
        __half* rowB = g_B + (size_t)(n0 + n) * KC + k0 + 2 * j;
        *(__half2*)(rowB)      = hp;
        *(__half2*)(rowB + DV) = lp;
    }
}

// ---------------------------------------------------------------------------
// 4. mma.sync GEMM: D[2048,4096] = A'[2048,1536] @ B'[4096,1536]^T + bias
//    128x128 tile/CTA, 8 warps x (64x32), KCHUNK=64, SW128 smem,
//    3-stage cp.async pipeline, 2 CTAs/SM, CTA-swizzled for L2 locality.
// ---------------------------------------------------------------------------
#define STAGE_BYTES 32768
#define SA_OFF(st) ((st) * STAGE_BYTES)
#define SB_OFF(st) ((st) * STAGE_BYTES + 16384)
#define SMEM_TOTAL (3 * STAGE_BYTES)    // 96 KB

__global__ void __launch_bounds__(256, 2)
gemm_mma_kernel(const float* __restrict__ bias, float* __restrict__ out) {
    extern __shared__ __align__(1024) char smem[];
    uint32_t sbase = smem_u32(smem);
    int tid = threadIdx.x;
    int wid = tid >> 5, lane = tid & 31;
    // swizzle: mblk inner -> 296 concurrent CTAs share all of A + ~18 B tiles
    int mblk = blockIdx.x & 15;          // 16
    int nblk = blockIdx.x >> 4;          // 32
    int m0 = mblk * TM, n0 = nblk * TN;
    int wm = (wid & 1) * 64;             // warp M offset
    int wn = (wid >> 1) * 32;            // warp N offset

    const __half* Abase = g_A + (size_t)m0 * KC;
    const __half* Bbase = g_B + (size_t)n0 * KC;

    // ldmatrix lane addressing
    int q = lane >> 3, r8 = lane & 7;
    int qm = (q & 1) * 8;
    int qk = (q >> 1) * 16;

    float acc[4][4][4];
    #pragma unroll
    for (int a = 0; a < 4; a++)
        #pragma unroll
        for (int b = 0; b < 4; b++)
            #pragma unroll
            for (int c = 0; c < 4; c++) acc[a][b][c] = 0.f;

    #define ISSUE(cc) do { \
        int _stg = (cc) % 3; \
        const __half* Ap = Abase + (size_t)(cc) * KCHUNK; \
        const __half* Bp = Bbase + (size_t)(cc) * KCHUNK; \
        _Pragma("unroll") \
        for (int i = 0; i < 4; i++) { \
            int f = tid + i * 256; \
            int row = f >> 3, j = f & 7; \
            int off = SW128(row * 128 + j * 16); \
            cp16(sbase + SA_OFF(_stg) + off, Ap + (size_t)row * KC + j * 8); \
            cp16(sbase + SB_OFF(_stg) + off, Bp + (size_t)row * KC + j * 8); \
        } \
    } while (0)

    ISSUE(0); CP_COMMIT();
    ISSUE(1); CP_COMMIT();

    #pragma unroll 1
    for (int c = 0; c < NCHUNK; c++) {
        if (c + 2 < NCHUNK) ISSUE(c + 2);
        CP_COMMIT();
        CP_WAIT2();                      // stage c's group complete
        __syncthreads();

        int st = c % 3;
        uint32_t abuf = sbase + SA_OFF(st);
        uint32_t bbuf = sbase + SB_OFF(st);
        #pragma unroll
        for (int ks = 0; ks < 4; ks++) {
            uint32_t afr[4][4], bfr[2][4];
            #pragma unroll
            for (int mt = 0; mt < 4; mt++)
                ldsm4(afr[mt], abuf + SW128((wm + mt * 16 + qm + r8) * 128 + ks * 32 + qk));
            #pragma unroll
            for (int nt = 0; nt < 2; nt++)
                ldsm4(bfr[nt], bbuf + SW128((wn + nt * 16 + qm + r8) * 128 + ks * 32 + qk));
            #pragma unroll
            for (int mt = 0; mt < 4; mt++)
                #pragma unroll
                for (int nf = 0; nf < 4; nf++) {
                    int nt = nf >> 1, half = nf & 1;
                    mma_f16(acc[mt][nf], afr[mt], bfr[nt][half], bfr[nt][half + 2]);
                }
        }
        __syncthreads();                 // all reads of buf st done
    }

    // epilogue: C frag m16n8: c0,c1=(row g, col 2i,2i+1); c2,c3=(row g+8)
    int g = lane >> 2, i2 = (lane & 3) * 2;
    #pragma unroll
    for (int mt = 0; mt < 4; mt++) {
        #pragma unroll
        for (int rh = 0; rh < 2; rh++) {
            int m = m0 + wm + mt * 16 + rh * 8 + g;
            int b = m >> 5, kk = m & 31;
            float* orow = out + (size_t)(b * OUT_S + kk) * DL + n0 + wn;
            #pragma unroll
            for (int nf = 0; nf < 4; nf++) {
                int n = nf * 8 + i2;
                float2 bb = *(const float2*)(bias + n0 + wn + n);
                float2 o;
                o.x = acc[mt][nf][rh * 2 + 0] + bb.x;
                o.y = acc[mt][nf][rh * 2 + 1] + bb.y;
                *(float2*)(orow + n) = o;
            }
        }
    }
}

// ---------------------------------------------------------------------------
// 5. Embedding gather: persistent grid-stride, 2 rows/iter (8 LDG.128 in
//    flight per thread), cached reads (L2 dedups repeated ids), streaming
//    stores. int64/int32 sniff is inlined per-block (ids < 32000 => int64
//    data has all odd words zero).
// ---------------------------------------------------------------------------
#define GATHER_BLOCKS 1184   // 148 SMs x 8 resident blocks
__global__ void __launch_bounds__(256)
gather_kernel(const int* __restrict__ ids32,
              const float* __restrict__ table,
              float* __restrict__ out) {
    __shared__ int s_is64;
    int tid = threadIdx.x;
    if (tid < 32) {
        unsigned nz = __ballot_sync(0xffffffffu, ids32[2 * tid + 1] != 0);
        if (tid == 0) s_is64 = (nz == 0u) ? 1 : 0;
    }
    __syncthreads();
    int is64 = s_is64;

    for (int r0 = blockIdx.x * 2; r0 < B_SZ * T_SZ; r0 += GATHER_BLOCKS * 2) {
        int r1 = r0 + 1;
        long long id0, id1;
        if (is64) {
            id0 = ((const long long*)ids32)[r0];
            id1 = ((const long long*)ids32)[r1];
        } else {
            id0 = (long long)ids32[r0];
            id1 = (long long)ids32[r1];
        }
        const float4* s0 = (const float4*)(table + (size_t)id0 * DL);
        const float4* s1 = (const float4*)(table + (size_t)id1 * DL);
        int b0 = r0 >> 9, t0 = r0 & 511;
        int b1 = r1 >> 9, t1 = r1 & 511;
        float4* d0 = (float4*)(out + (size_t)(b0 * OUT_S + TOPK + t0) * DL);
        float4* d1 = (float4*)(out + (size_t)(b1 * OUT_S + TOPK + t1) * DL);

        float4 a0 = s0[tid];
        float4 a1 = s0[tid + 256];
        float4 a2 = s0[tid + 512];
        float4 a3 = s0[tid + 768];
        float4 c0 = s1[tid];
        float4 c1 = s1[tid + 256];
        float4 c2 = s1[tid + 512];
        float4 c3 = s1[tid + 768];
        __stcs(d0 + tid,       a0);
        __stcs(d0 + tid + 256, a1);
        __stcs(d0 + tid + 512, a2);
        __stcs(d0 + tid + 768, a3);
        __stcs(d1 + tid,       c0);
        __stcs(d1 + tid + 256, c1);
        __stcs(d1 + tid + 512, c2);
        __stcs(d1 + tid + 768, c3);
    }
}

// ---------------------------------------------------------------------------
// kernel_launch: fork immediately; s2 = gather (self-sniffing), s3 = convertB,
// main = scores -> topk -> convA -> (wait convertB) -> cp.async mma GEMM.
// metadata order: vision_tokens, input_ids, ln_gamma, ln_beta, scorer_w,
//                 scorer_b, proj_w, proj_b, embed_table
// ---------------------------------------------------------------------------
extern "C" void kernel_launch(void* const* d_in, const int* in_sizes, int n_in,
                              void* d_out, int out_size) {
    const float* vision_tokens = (const float*)d_in[0];
    const void*  input_ids     = d_in[1];
    const float* ln_gamma      = (const float*)d_in[2];
    const float* scorer_w      = (const float*)d_in[4];
    const float* proj_w        = (const float*)d_in[6];
    const float* proj_b        = (const float*)d_in[7];
    const float* embed_table   = (const float*)d_in[8];
    float* out = (float*)d_out;

    static cudaStream_t s2 = nullptr, s3 = nullptr;
    static cudaEvent_t eFork = nullptr, eB = nullptr, eG = nullptr;
    if (s2 == nullptr) {
        cudaStreamCreateWithFlags(&s2, cudaStreamNonBlocking);
        cudaStreamCreateWithFlags(&s3, cudaStreamNonBlocking);
        cudaEventCreateWithFlags(&eFork, cudaEventDisableTiming);
        cudaEventCreateWithFlags(&eB, cudaEventDisableTiming);
        cudaEventCreateWithFlags(&eG, cudaEventDisableTiming);
        cudaFuncSetAttribute(gemm_mma_kernel,
                             cudaFuncAttributeMaxDynamicSharedMemorySize, SMEM_TOTAL);
    }

    cudaEventRecord(eFork, 0);
    cudaStreamWaitEvent(s2, eFork, 0);
    cudaStreamWaitEvent(s3, eFork, 0);

    // stream s2: the big DRAM-bound gather, starting immediately
    gather_kernel<<<GATHER_BLOCKS, 256, 0, s2>>>((const int*)input_ids,
                                                 embed_table, out);
    cudaEventRecord(eG, s2);

    // stream s3: B conversion for the GEMM
    {
        dim3 gb(DL / 32, DV / 32);    // 128 x 24
        convertB_kernel<<<gb, 256, 0, s3>>>(proj_w);
    }
    cudaEventRecord(eB, s3);

    // main stream: scoring chain -> GEMM
    scores_kernel<<<(B_SZ * P_SZ * 32 + 255) / 256, 256>>>(vision_tokens, ln_gamma, scorer_w);
    topk_kernel<<<(B_SZ * 32 + 255) / 256, 256>>>();
    convertA_kernel<<<M_TOT, 128>>>(vision_tokens);
    cudaStreamWaitEvent(0, eB, 0);
    gemm_mma_kernel<<<(M_TOT / TM) * (DL / TN), 256, SMEM_TOTAL>>>(proj_b, out);

    cudaStreamWaitEvent(0, eG, 0);
}

// round 11
// speedup vs baseline: 3.3710x; 1.1907x over previous
#include <cuda_runtime.h>
#include <cuda_fp16.h>
#include <float.h>
#include <stdint.h>

// ---------------------------------------------------------------------------
// Problem constants (fixed shapes for SparseVLMModel_59725815218738)
// ---------------------------------------------------------------------------
#define B_SZ    64
#define S_SZ    197
#define P_SZ    196
#define T_SZ    512
#define DV      768
#define DL      4096
#define TOPK    32
#define OUT_S   (TOPK + T_SZ)   // 544
#define LN_EPS  1e-5f

#define M_TOT   (B_SZ * TOPK)   // 2048
#define KC      DV              // 768: plain fp16 GEMM (A,B rounded to fp16)
#define TM      128
#define TN      128
#define KCHUNK  64
#define NCHUNK  (KC / KCHUNK)   // 12

// Scratch (no cudaMalloc allowed)
__device__ float g_scores[B_SZ * P_SZ];
__device__ int   g_topk[M_TOT];
__device__ __align__(128) __half g_A[(size_t)M_TOT * KC]; // 3.1 MB
__device__ __align__(128) __half g_B[(size_t)DL * KC];    // 6.3 MB

__device__ __forceinline__ uint32_t smem_u32(const void* p) {
    uint32_t a;
    asm("{ .reg .u64 t; cvta.to.shared.u64 t, %1; cvt.u32.u64 %0, t; }" : "=r"(a) : "l"(p));
    return a;
}
__device__ __forceinline__ void ldsm4(uint32_t* r, uint32_t addr) {
    asm volatile("ldmatrix.sync.aligned.m8n8.x4.shared.b16 {%0,%1,%2,%3}, [%4];"
                 : "=r"(r[0]), "=r"(r[1]), "=r"(r[2]), "=r"(r[3]) : "r"(addr));
}
__device__ __forceinline__ void mma_f16(float* c, const uint32_t* a,
                                        uint32_t b0, uint32_t b1) {
    asm volatile(
        "mma.sync.aligned.m16n8k16.row.col.f32.f16.f16.f32 "
        "{%0,%1,%2,%3}, {%4,%5,%6,%7}, {%8,%9}, {%0,%1,%2,%3};"
        : "+f"(c[0]), "+f"(c[1]), "+f"(c[2]), "+f"(c[3])
        : "r"(a[0]), "r"(a[1]), "r"(a[2]), "r"(a[3]), "r"(b0), "r"(b1));
}
__device__ __forceinline__ void cp16(uint32_t saddr, const void* g) {
    asm volatile("cp.async.cg.shared.global [%0], [%1], 16;"
                 :: "r"(saddr), "l"(g) : "memory");
}
#define CP_COMMIT() asm volatile("cp.async.commit_group;" ::: "memory")
#define CP_WAIT2()  asm volatile("cp.async.wait_group 2;" ::: "memory")
#define SW128(x) ((x) ^ (((x) >> 3) & 0x70))

// ---------------------------------------------------------------------------
// 1. Scores: warp-per-row LayerNorm dot (ordering-equivalent form)
// ---------------------------------------------------------------------------
__global__ void __launch_bounds__(256)
scores_kernel(const float* __restrict__ vt,
              const float* __restrict__ gamma,
              const float* __restrict__ w) {
    int warp = (blockIdx.x * 256 + threadIdx.x) >> 5;
    int lane = threadIdx.x & 31;
    if (warp >= B_SZ * P_SZ) return;
    int b = warp / P_SZ, s = warp % P_SZ;
    const float4* x4 = (const float4*)(vt + (size_t)(b * S_SZ + 1 + s) * DV);
    const float4* g4 = (const float4*)gamma;
    const float4* w4 = (const float4*)w;

    float s1 = 0.f, s2 = 0.f, sgw = 0.f, cgw = 0.f;
    #pragma unroll
    for (int i = 0; i < 6; i++) {
        int idx = lane + i * 32;
        float4 xv = x4[idx];
        float4 gv = g4[idx];
        float4 wv = w4[idx];
        float gw0 = gv.x * wv.x, gw1 = gv.y * wv.y, gw2 = gv.z * wv.z, gw3 = gv.w * wv.w;
        s1 += xv.x + xv.y + xv.z + xv.w;
        s2 += xv.x * xv.x + xv.y * xv.y + xv.z * xv.z + xv.w * xv.w;
        sgw += xv.x * gw0 + xv.y * gw1 + xv.z * gw2 + xv.w * gw3;
        cgw += gw0 + gw1 + gw2 + gw3;
    }
    #pragma unroll
    for (int st = 16; st > 0; st >>= 1) {
        s1  += __shfl_xor_sync(0xffffffffu, s1, st);
        s2  += __shfl_xor_sync(0xffffffffu, s2, st);
        sgw += __shfl_xor_sync(0xffffffffu, sgw, st);
        cgw += __shfl_xor_sync(0xffffffffu, cgw, st);
    }
    if (lane == 0) {
        float mean = s1 * (1.0f / DV);
        float var  = s2 * (1.0f / DV) - mean * mean;
        float rstd = rsqrtf(var + LN_EPS);
        g_scores[warp] = rstd * (sgw - mean * cgw);
    }
}

// ---------------------------------------------------------------------------
// 2. Top-32 per batch: warp-per-batch register argmax, stable ties.
// ---------------------------------------------------------------------------
__global__ void __launch_bounds__(256)
topk_kernel() {
    int warp = (blockIdx.x * 256 + threadIdx.x) >> 5;   // 0..63
    int lane = threadIdx.x & 31;
    if (warp >= B_SZ) return;
    float v[7];
    #pragma unroll
    for (int i = 0; i < 7; i++) {
        int idx = lane + i * 32;
        v[i] = (idx < P_SZ) ? g_scores[warp * P_SZ + idx] : -FLT_MAX;
    }
    for (int k = 0; k < TOPK; k++) {
        float best = -FLT_MAX; int bi = 0;
        #pragma unroll
        for (int i = 0; i < 7; i++)
            if (v[i] > best) { best = v[i]; bi = i; }    // ascending idx: stable
        int bidx = lane + bi * 32;
        #pragma unroll
        for (int st = 16; st > 0; st >>= 1) {
            float ov = __shfl_xor_sync(0xffffffffu, best, st);
            int   oi = __shfl_xor_sync(0xffffffffu, bidx, st);
            if (ov > best || (ov == best && oi < bidx)) { best = ov; bidx = oi; }
        }
        if (lane == 0) g_topk[warp * TOPK + k] = bidx;
        if ((bidx & 31) == lane) v[bidx >> 5] = -FLT_MAX;
    }
}

// ---------------------------------------------------------------------------
// 3a. Convert gathered A rows fp32 -> fp16 (single term, K = 768)
// ---------------------------------------------------------------------------
__global__ void __launch_bounds__(128)
convertA_kernel(const float* __restrict__ vt) {
    int m = blockIdx.x;                // 0..2047
    int b = m >> 5;
    size_t base = (size_t)(b * S_SZ + 1 + g_topk[m]) * DV;
    __half* rowA = g_A + (size_t)m * KC;
    int t = threadIdx.x;
    #pragma unroll
    for (int i = 0; i < 3; i++) {
        int p = t + i * 128;           // pair 0..383
        float v0 = vt[base + 2 * p], v1 = vt[base + 2 * p + 1];
        __half2 hp;
        hp.x = __float2half_rn(v0);
        hp.y = __float2half_rn(v1);
        *(__half2*)(rowA + 2 * p) = hp;
    }
}

// ---------------------------------------------------------------------------
// 3b. Convert+transpose proj_w [768,4096] -> g_B [4096][768] fp16
// ---------------------------------------------------------------------------
__global__ void __launch_bounds__(256)
convertB_kernel(const float* __restrict__ W) {
    __shared__ float tile[32][33];
    int n0 = blockIdx.x * 32;          // 128 blocks
    int k0 = blockIdx.y * 32;          // 24 blocks
    int t = threadIdx.x;
    #pragma unroll
    for (int i = 0; i < 4; i++) {
        int e = t + i * 256;
        int r = e >> 5, c = e & 31;
        tile[r][c] = W[(size_t)(k0 + r) * DL + n0 + c];
    }
    __syncthreads();
    #pragma unroll
    for (int i = 0; i < 2; i++) {
        int n = (t >> 4) + i * 16;
        int j = t & 15;
        __half2 hp;
        hp.x = __float2half_rn(tile[2 * j][n]);
        hp.y = __float2half_rn(tile[2 * j + 1][n]);
        *(__half2*)(g_B + (size_t)(n0 + n) * KC + k0 + 2 * j) = hp;
    }
}

// ---------------------------------------------------------------------------
// 4. mma.sync GEMM: D[2048,4096] = A[2048,768] @ B[4096,768]^T + bias
//    128x128 tile/CTA, 8 warps x (64x32), KCHUNK=64, SW128 smem,
//    3-stage cp.async pipeline, 2 CTAs/SM, CTA-swizzled for L2 locality.
// ---------------------------------------------------------------------------
#define STAGE_BYTES 32768
#define SA_OFF(st) ((st) * STAGE_BYTES)
#define SB_OFF(st) ((st) * STAGE_BYTES + 16384)
#define SMEM_TOTAL (3 * STAGE_BYTES)    // 96 KB

__global__ void __launch_bounds__(256, 2)
gemm_mma_kernel(const float* __restrict__ bias, float* __restrict__ out) {
    extern __shared__ __align__(1024) char smem[];
    uint32_t sbase = smem_u32(smem);
    int tid = threadIdx.x;
    int wid = tid >> 5, lane = tid & 31;
    // swizzle: mblk inner -> 296 concurrent CTAs share all of A + ~18 B tiles
    int mblk = blockIdx.x & 15;          // 16
    int nblk = blockIdx.x >> 4;          // 32
    int m0 = mblk * TM, n0 = nblk * TN;
    int wm = (wid & 1) * 64;             // warp M offset
    int wn = (wid >> 1) * 32;            // warp N offset

    const __half* Abase = g_A + (size_t)m0 * KC;
    const __half* Bbase = g_B + (size_t)n0 * KC;

    // ldmatrix lane addressing
    int q = lane >> 3, r8 = lane & 7;
    int qm = (q & 1) * 8;
    int qk = (q >> 1) * 16;

    float acc[4][4][4];
    #pragma unroll
    for (int a = 0; a < 4; a++)
        #pragma unroll
        for (int b = 0; b < 4; b++)
            #pragma unroll
            for (int c = 0; c < 4; c++) acc[a][b][c] = 0.f;

    #define ISSUE(cc) do { \
        int _stg = (cc) % 3; \
        const __half* Ap = Abase + (size_t)(cc) * KCHUNK; \
        const __half* Bp = Bbase + (size_t)(cc) * KCHUNK; \
        _Pragma("unroll") \
        for (int i = 0; i < 4; i++) { \
            int f = tid + i * 256; \
            int row = f >> 3, j = f & 7; \
            int off = SW128(row * 128 + j * 16); \
            cp16(sbase + SA_OFF(_stg) + off, Ap + (size_t)row * KC + j * 8); \
            cp16(sbase + SB_OFF(_stg) + off, Bp + (size_t)row * KC + j * 8); \
        } \
    } while (0)

    ISSUE(0); CP_COMMIT();
    ISSUE(1); CP_COMMIT();

    #pragma unroll 1
    for (int c = 0; c < NCHUNK; c++) {
        if (c + 2 < NCHUNK) ISSUE(c + 2);
        CP_COMMIT();
        CP_WAIT2();                      // stage c's group complete
        __syncthreads();

        int st = c % 3;
        uint32_t abuf = sbase + SA_OFF(st);
        uint32_t bbuf = sbase + SB_OFF(st);
        #pragma unroll
        for (int ks = 0; ks < 4; ks++) {
            uint32_t afr[4][4], bfr[2][4];
            #pragma unroll
            for (int mt = 0; mt < 4; mt++)
                ldsm4(afr[mt], abuf + SW128((wm + mt * 16 + qm + r8) * 128 + ks * 32 + qk));
            #pragma unroll
            for (int nt = 0; nt < 2; nt++)
                ldsm4(bfr[nt], bbuf + SW128((wn + nt * 16 + qm + r8) * 128 + ks * 32 + qk));
            #pragma unroll
            for (int mt = 0; mt < 4; mt++)
                #pragma unroll
                for (int nf = 0; nf < 4; nf++) {
                    int nt = nf >> 1, half = nf & 1;
                    mma_f16(acc[mt][nf], afr[mt], bfr[nt][half], bfr[nt][half + 2]);
                }
        }
        __syncthreads();                 // all reads of buf st done
    }

    // epilogue: C frag m16n8: c0,c1=(row g, col 2i,2i+1); c2,c3=(row g+8)
    int g = lane >> 2, i2 = (lane & 3) * 2;
    #pragma unroll
    for (int mt = 0; mt < 4; mt++) {
        #pragma unroll
        for (int rh = 0; rh < 2; rh++) {
            int m = m0 + wm + mt * 16 + rh * 8 + g;
            int b = m >> 5, kk = m & 31;
            float* orow = out + (size_t)(b * OUT_S + kk) * DL + n0 + wn;
            #pragma unroll
            for (int nf = 0; nf < 4; nf++) {
                int n = nf * 8 + i2;
                float2 bb = *(const float2*)(bias + n0 + wn + n);
                float2 o;
                o.x = acc[mt][nf][rh * 2 + 0] + bb.x;
                o.y = acc[mt][nf][rh * 2 + 1] + bb.y;
                *(float2*)(orow + n) = o;
            }
        }
    }
}

// ---------------------------------------------------------------------------
// 5. Embedding gather: persistent grid-stride, 4 rows/iter (16 LDG.128 in
//    flight per thread), cached reads (L2 dedups repeated ids), streaming
//    stores. int64/int32 sniff inlined per-block (ids < 32000 => int64 data
//    has all odd words zero).
// ---------------------------------------------------------------------------
#define GATHER_BLOCKS 1184   // 148 SMs x 8 resident blocks
__global__ void __launch_bounds__(256)
gather_kernel(const int* __restrict__ ids32,
              const float* __restrict__ table,
              float* __restrict__ out) {
    __shared__ int s_is64;
    int tid = threadIdx.x;
    if (tid < 32) {
        unsigned nz = __ballot_sync(0xffffffffu, ids32[2 * tid + 1] != 0);
        if (tid == 0) s_is64 = (nz == 0u) ? 1 : 0;
    }
    __syncthreads();
    int is64 = s_is64;

    for (int r0 = blockIdx.x * 4; r0 < B_SZ * T_SZ; r0 += GATHER_BLOCKS * 4) {
        const float4* src[4];
        float4* dst[4];
        #pragma unroll
        for (int k = 0; k < 4; k++) {
            int r = r0 + k;
            long long id = is64 ? ((const long long*)ids32)[r]
                                : (long long)ids32[r];
            src[k] = (const float4*)(table + (size_t)id * DL);
            dst[k] = (float4*)(out + (size_t)((r >> 9) * OUT_S + TOPK + (r & 511)) * DL);
        }
        float4 v[4][4];
        #pragma unroll
        for (int k = 0; k < 4; k++)
            #pragma unroll
            for (int i = 0; i < 4; i++)
                v[k][i] = src[k][tid + i * 256];
        #pragma unroll
        for (int k = 0; k < 4; k++)
            #pragma unroll
            for (int i = 0; i < 4; i++)
                __stcs(dst[k] + tid + i * 256, v[k][i]);
    }
}

// ---------------------------------------------------------------------------
// kernel_launch: fork immediately; s2 = gather (self-sniffing), s3 = convertB,
// main = scores -> topk -> convA -> (wait convertB) -> cp.async mma GEMM.
// metadata order: vision_tokens, input_ids, ln_gamma, ln_beta, scorer_w,
//                 scorer_b, proj_w, proj_b, embed_table
// ---------------------------------------------------------------------------
extern "C" void kernel_launch(void* const* d_in, const int* in_sizes, int n_in,
                              void* d_out, int out_size) {
    const float* vision_tokens = (const float*)d_in[0];
    const void*  input_ids     = d_in[1];
    const float* ln_gamma      = (const float*)d_in[2];
    const float* scorer_w      = (const float*)d_in[4];
    const float* proj_w        = (const float*)d_in[6];
    const float* proj_b        = (const float*)d_in[7];
    const float* embed_table   = (const float*)d_in[8];
    float* out = (float*)d_out;

    static cudaStream_t s2 = nullptr, s3 = nullptr;
    static cudaEvent_t eFork = nullptr, eB = nullptr, eG = nullptr;
    if (s2 == nullptr) {
        cudaStreamCreateWithFlags(&s2, cudaStreamNonBlocking);
        cudaStreamCreateWithFlags(&s3, cudaStreamNonBlocking);
        cudaEventCreateWithFlags(&eFork, cudaEventDisableTiming);
        cudaEventCreateWithFlags(&eB, cudaEventDisableTiming);
        cudaEventCreateWithFlags(&eG, cudaEventDisableTiming);
        cudaFuncSetAttribute(gemm_mma_kernel,
                             cudaFuncAttributeMaxDynamicSharedMemorySize, SMEM_TOTAL);
    }

    cudaEventRecord(eFork, 0);
    cudaStreamWaitEvent(s2, eFork, 0);
    cudaStreamWaitEvent(s3, eFork, 0);

    // stream s2: the big DRAM-bound gather, starting immediately
    gather_kernel<<<GATHER_BLOCKS, 256, 0, s2>>>((const int*)input_ids,
                                                 embed_table, out);
    cudaEventRecord(eG, s2);

    // stream s3: B conversion for the GEMM
    {
        dim3 gb(DL / 32, DV / 32);    // 128 x 24
        convertB_kernel<<<gb, 256, 0, s3>>>(proj_w);
    }
    cudaEventRecord(eB, s3);

    // main stream: scoring chain -> GEMM
    scores_kernel<<<(B_SZ * P_SZ * 32 + 255) / 256, 256>>>(vision_tokens, ln_gamma, scorer_w);
    topk_kernel<<<(B_SZ * 32 + 255) / 256, 256>>>();
    convertA_kernel<<<M_TOT, 128>>>(vision_tokens);
    cudaStreamWaitEvent(0, eB, 0);
    gemm_mma_kernel<<<(M_TOT / TM) * (DL / TN), 256, SMEM_TOTAL>>>(proj_b, out);

    cudaStreamWaitEvent(0, eG, 0);
}

// round 12
// speedup vs baseline: 3.5836x; 1.0631x over previous
#include <cuda_runtime.h>
#include <cuda_fp16.h>
#include <float.h>
#include <stdint.h>

// ---------------------------------------------------------------------------
// Problem constants (fixed shapes for SparseVLMModel_59725815218738)
// ---------------------------------------------------------------------------
#define B_SZ    64
#define S_SZ    197
#define P_SZ    196
#define T_SZ    512
#define DV      768
#define DL      4096
#define TOPK    32
#define OUT_S   (TOPK + T_SZ)   // 544
#define LN_EPS  1e-5f
#define VOCAB   32000
#define NROWS   (B_SZ * T_SZ)   // 32768

#define M_TOT   (B_SZ * TOPK)   // 2048
#define KC      DV              // 768: plain fp16 GEMM (A,B rounded to fp16)
#define TM      128
#define TN      128
#define KCHUNK  64
#define NCHUNK  (KC / KCHUNK)   // 12

// Scratch (no cudaMalloc allowed)
__device__ float g_scores[B_SZ * P_SZ];
__device__ int   g_topk[M_TOT];
__device__ int   g_hist[VOCAB];
__device__ int   g_perm[NROWS];
__device__ __align__(128) __half g_A[(size_t)M_TOT * KC]; // 3.1 MB
__device__ __align__(128) __half g_B[(size_t)DL * KC];    // 6.3 MB

__device__ __forceinline__ uint32_t smem_u32(const void* p) {
    uint32_t a;
    asm("{ .reg .u64 t; cvta.to.shared.u64 t, %1; cvt.u32.u64 %0, t; }" : "=r"(a) : "l"(p));
    return a;
}
__device__ __forceinline__ void ldsm4(uint32_t* r, uint32_t addr) {
    asm volatile("ldmatrix.sync.aligned.m8n8.x4.shared.b16 {%0,%1,%2,%3}, [%4];"
                 : "=r"(r[0]), "=r"(r[1]), "=r"(r[2]), "=r"(r[3]) : "r"(addr));
}
__device__ __forceinline__ void mma_f16(float* c, const uint32_t* a,
                                        uint32_t b0, uint32_t b1) {
    asm volatile(
        "mma.sync.aligned.m16n8k16.row.col.f32.f16.f16.f32 "
        "{%0,%1,%2,%3}, {%4,%5,%6,%7}, {%8,%9}, {%0,%1,%2,%3};"
        : "+f"(c[0]), "+f"(c[1]), "+f"(c[2]), "+f"(c[3])
        : "r"(a[0]), "r"(a[1]), "r"(a[2]), "r"(a[3]), "r"(b0), "r"(b1));
}
__device__ __forceinline__ void cp16(uint32_t saddr, const void* g) {
    asm volatile("cp.async.cg.shared.global [%0], [%1], 16;"
                 :: "r"(saddr), "l"(g) : "memory");
}
#define CP_COMMIT() asm volatile("cp.async.commit_group;" ::: "memory")
#define CP_WAIT2()  asm volatile("cp.async.wait_group 2;" ::: "memory")
#define SW128(x) ((x) ^ (((x) >> 3) & 0x70))

// Per-block int64/int32 sniff: ids < 32000, so int64 => all odd words zero.
__device__ __forceinline__ int sniff_is64(const int* __restrict__ ids32) {
    unsigned nz = __ballot_sync(0xffffffffu,
                                ids32[2 * (threadIdx.x & 31) + 1] != 0);
    return (nz == 0u) ? 1 : 0;
}
__device__ __forceinline__ long long load_id(const int* __restrict__ ids32,
                                             int r, int is64) {
    return is64 ? ((const long long*)ids32)[r] : (long long)ids32[r];
}

// ---------------------------------------------------------------------------
// 1. Scores: warp-per-row LayerNorm dot (ordering-equivalent form)
// ---------------------------------------------------------------------------
__global__ void __launch_bounds__(256)
scores_kernel(const float* __restrict__ vt,
              const float* __restrict__ gamma,
              const float* __restrict__ w) {
    int warp = (blockIdx.x * 256 + threadIdx.x) >> 5;
    int lane = threadIdx.x & 31;
    if (warp >= B_SZ * P_SZ) return;
    int b = warp / P_SZ, s = warp % P_SZ;
    const float4* x4 = (const float4*)(vt + (size_t)(b * S_SZ + 1 + s) * DV);
    const float4* g4 = (const float4*)gamma;
    const float4* w4 = (const float4*)w;

    float s1 = 0.f, s2 = 0.f, sgw = 0.f, cgw = 0.f;
    #pragma unroll
    for (int i = 0; i < 6; i++) {
        int idx = lane + i * 32;
        float4 xv = x4[idx];
        float4 gv = g4[idx];
        float4 wv = w4[idx];
        float gw0 = gv.x * wv.x, gw1 = gv.y * wv.y, gw2 = gv.z * wv.z, gw3 = gv.w * wv.w;
        s1 += xv.x + xv.y + xv.z + xv.w;
        s2 += xv.x * xv.x + xv.y * xv.y + xv.z * xv.z + xv.w * xv.w;
        sgw += xv.x * gw0 + xv.y * gw1 + xv.z * gw2 + xv.w * gw3;
        cgw += gw0 + gw1 + gw2 + gw3;
    }
    #pragma unroll
    for (int st = 16; st > 0; st >>= 1) {
        s1  += __shfl_xor_sync(0xffffffffu, s1, st);
        s2  += __shfl_xor_sync(0xffffffffu, s2, st);
        sgw += __shfl_xor_sync(0xffffffffu, sgw, st);
        cgw += __shfl_xor_sync(0xffffffffu, cgw, st);
    }
    if (lane == 0) {
        float mean = s1 * (1.0f / DV);
        float var  = s2 * (1.0f / DV) - mean * mean;
        float rstd = rsqrtf(var + LN_EPS);
        g_scores[warp] = rstd * (sgw - mean * cgw);
    }
}

// ---------------------------------------------------------------------------
// 2. Top-32 per batch: warp-per-batch register argmax, stable ties.
// ---------------------------------------------------------------------------
__global__ void __launch_bounds__(256)
topk_kernel() {
    int warp = (blockIdx.x * 256 + threadIdx.x) >> 5;   // 0..63
    int lane = threadIdx.x & 31;
    if (warp >= B_SZ) return;
    float v[7];
    #pragma unroll
    for (int i = 0; i < 7; i++) {
        int idx = lane + i * 32;
        v[i] = (idx < P_SZ) ? g_scores[warp * P_SZ + idx] : -FLT_MAX;
    }
    for (int k = 0; k < TOPK; k++) {
        float best = -FLT_MAX; int bi = 0;
        #pragma unroll
        for (int i = 0; i < 7; i++)
            if (v[i] > best) { best = v[i]; bi = i; }    // ascending idx: stable
        int bidx = lane + bi * 32;
        #pragma unroll
        for (int st = 16; st > 0; st >>= 1) {
            float ov = __shfl_xor_sync(0xffffffffu, best, st);
            int   oi = __shfl_xor_sync(0xffffffffu, bidx, st);
            if (ov > best || (ov == best && oi < bidx)) { best = ov; bidx = oi; }
        }
        if (lane == 0) g_topk[warp * TOPK + k] = bidx;
        if ((bidx & 31) == lane) v[bidx >> 5] = -FLT_MAX;
    }
}

// ---------------------------------------------------------------------------
// 3a. Convert gathered A rows fp32 -> fp16 (single term, K = 768)
// ---------------------------------------------------------------------------
__global__ void __launch_bounds__(128)
convertA_kernel(const float* __restrict__ vt) {
    int m = blockIdx.x;                // 0..2047
    int b = m >> 5;
    size_t base = (size_t)(b * S_SZ + 1 + g_topk[m]) * DV;
    __half* rowA = g_A + (size_t)m * KC;
    int t = threadIdx.x;
    #pragma unroll
    for (int i = 0; i < 3; i++) {
        int p = t + i * 128;           // pair 0..383
        float v0 = vt[base + 2 * p], v1 = vt[base + 2 * p + 1];
        __half2 hp;
        hp.x = __float2half_rn(v0);
        hp.y = __float2half_rn(v1);
        *(__half2*)(rowA + 2 * p) = hp;
    }
}

// ---------------------------------------------------------------------------
// 3b. Convert+transpose proj_w [768,4096] -> g_B [4096][768] fp16
// ---------------------------------------------------------------------------
__global__ void __launch_bounds__(256)
convertB_kernel(const float* __restrict__ W) {
    __shared__ float tile[32][33];
    int n0 = blockIdx.x * 32;          // 128 blocks
    int k0 = blockIdx.y * 32;          // 24 blocks
    int t = threadIdx.x;
    #pragma unroll
    for (int i = 0; i < 4; i++) {
        int e = t + i * 256;
        int r = e >> 5, c = e & 31;
        tile[r][c] = W[(size_t)(k0 + r) * DL + n0 + c];
    }
    __syncthreads();
    #pragma unroll
    for (int i = 0; i < 2; i++) {
        int n = (t >> 4) + i * 16;
        int j = t & 15;
        __half2 hp;
        hp.x = __float2half_rn(tile[2 * j][n]);
        hp.y = __float2half_rn(tile[2 * j + 1][n]);
        *(__half2*)(g_B + (size_t)(n0 + n) * KC + k0 + 2 * j) = hp;
    }
}

// ---------------------------------------------------------------------------
// 4. mma.sync GEMM: D[2048,4096] = A[2048,768] @ B[4096,768]^T + bias
//    128x128 tile/CTA, 8 warps x (64x32), KCHUNK=64, SW128 smem,
//    3-stage cp.async pipeline, 2 CTAs/SM, CTA-swizzled for L2 locality.
// ---------------------------------------------------------------------------
#define STAGE_BYTES 32768
#define SA_OFF(st) ((st) * STAGE_BYTES)
#define SB_OFF(st) ((st) * STAGE_BYTES + 16384)
#define SMEM_TOTAL (3 * STAGE_BYTES)    // 96 KB

__global__ void __launch_bounds__(256, 2)
gemm_mma_kernel(const float* __restrict__ bias, float* __restrict__ out) {
    extern __shared__ __align__(1024) char smem[];
    uint32_t sbase = smem_u32(smem);
    int tid = threadIdx.x;
    int wid = tid >> 5, lane = tid & 31;
    // swizzle: mblk inner -> 296 concurrent CTAs share all of A + ~18 B tiles
    int mblk = blockIdx.x & 15;          // 16
    int nblk = blockIdx.x >> 4;          // 32
    int m0 = mblk * TM, n0 = nblk * TN;
    int wm = (wid & 1) * 64;             // warp M offset
    int wn = (wid >> 1) * 32;            // warp N offset

    const __half* Abase = g_A + (size_t)m0 * KC;
    const __half* Bbase = g_B + (size_t)n0 * KC;

    // ldmatrix lane addressing
    int q = lane >> 3, r8 = lane & 7;
    int qm = (q & 1) * 8;
    int qk = (q >> 1) * 16;

    float acc[4][4][4];
    #pragma unroll
    for (int a = 0; a < 4; a++)
        #pragma unroll
        for (int b = 0; b < 4; b++)
            #pragma unroll
            for (int c = 0; c < 4; c++) acc[a][b][c] = 0.f;

    #define ISSUE(cc) do { \
        int _stg = (cc) % 3; \
        const __half* Ap = Abase + (size_t)(cc) * KCHUNK; \
        const __half* Bp = Bbase + (size_t)(cc) * KCHUNK; \
        _Pragma("unroll") \
        for (int i = 0; i < 4; i++) { \
            int f = tid + i * 256; \
            int row = f >> 3, j = f & 7; \
            int off = SW128(row * 128 + j * 16); \
            cp16(sbase + SA_OFF(_stg) + off, Ap + (size_t)row * KC + j * 8); \
            cp16(sbase + SB_OFF(_stg) + off, Bp + (size_t)row * KC + j * 8); \
        } \
    } while (0)

    ISSUE(0); CP_COMMIT();
    ISSUE(1); CP_COMMIT();

    #pragma unroll 1
    for (int c = 0; c < NCHUNK; c++) {
        if (c + 2 < NCHUNK) ISSUE(c + 2);
        CP_COMMIT();
        CP_WAIT2();                      // stage c's group complete
        __syncthreads();

        int st = c % 3;
        uint32_t abuf = sbase + SA_OFF(st);
        uint32_t bbuf = sbase + SB_OFF(st);
        #pragma unroll
        for (int ks = 0; ks < 4; ks++) {
            uint32_t afr[4][4], bfr[2][4];
            #pragma unroll
            for (int mt = 0; mt < 4; mt++)
                ldsm4(afr[mt], abuf + SW128((wm + mt * 16 + qm + r8) * 128 + ks * 32 + qk));
            #pragma unroll
            for (int nt = 0; nt < 2; nt++)
                ldsm4(bfr[nt], bbuf + SW128((wn + nt * 16 + qm + r8) * 128 + ks * 32 + qk));
            #pragma unroll
            for (int mt = 0; mt < 4; mt++)
                #pragma unroll
                for (int nf = 0; nf < 4; nf++) {
                    int nt = nf >> 1, half = nf & 1;
                    mma_f16(acc[mt][nf], afr[mt], bfr[nt][half], bfr[nt][half + 2]);
                }
        }
        __syncthreads();                 // all reads of buf st done
    }

    // epilogue: C frag m16n8: c0,c1=(row g, col 2i,2i+1); c2,c3=(row g+8)
    int g = lane >> 2, i2 = (lane & 3) * 2;
    #pragma unroll
    for (int mt = 0; mt < 4; mt++) {
        #pragma unroll
        for (int rh = 0; rh < 2; rh++) {
            int m = m0 + wm + mt * 16 + rh * 8 + g;
            int b = m >> 5, kk = m & 31;
            float* orow = out + (size_t)(b * OUT_S + kk) * DL + n0 + wn;
            #pragma unroll
            for (int nf = 0; nf < 4; nf++) {
                int n = nf * 8 + i2;
                float2 bb = *(const float2*)(bias + n0 + wn + n);
                float2 o;
                o.x = acc[mt][nf][rh * 2 + 0] + bb.x;
                o.y = acc[mt][nf][rh * 2 + 1] + bb.y;
                *(float2*)(orow + n) = o;
            }
        }
    }
}

// ---------------------------------------------------------------------------
// 5a-5d. Counting sort of rows by id -> g_perm (ascending id order).
//    Duplicate ids land adjacent => gather's second read L2-hits, and the
//    table read stream becomes quasi-sequential. Within-id order is
//    nondeterministic (atomics) but harmless: identical source bytes.
// ---------------------------------------------------------------------------
__global__ void __launch_bounds__(256)
hist_zero_kernel() {
    int i = blockIdx.x * 256 + threadIdx.x;
    if (i < VOCAB) g_hist[i] = 0;
}
__global__ void __launch_bounds__(256)
hist_count_kernel(const int* __restrict__ ids32) {
    int is64 = sniff_is64(ids32);
    int r = blockIdx.x * 256 + threadIdx.x;
    if (r < NROWS) atomicAdd(&g_hist[(int)load_id(ids32, r, is64)], 1);
}
__global__ void __launch_bounds__(1024)
hist_scan_kernel() {
    __shared__ int ssum[1024];
    int t = threadIdx.x;
    int cnt[32];
    int base = t * 32;
    int local = 0;
    #pragma unroll
    for (int i = 0; i < 32; i++) {
        int idx = base + i;
        cnt[i] = (idx < VOCAB) ? g_hist[idx] : 0;
        local += cnt[i];
    }
    ssum[t] = local;
    __syncthreads();
    // Kogge-Stone inclusive scan over 1024 partials
    for (int st = 1; st < 1024; st <<= 1) {
        int v = (t >= st) ? ssum[t - st] : 0;
        __syncthreads();
        ssum[t] += v;
        __syncthreads();
    }
    int run = (t > 0) ? ssum[t - 1] : 0;   // exclusive prefix of this chunk
    #pragma unroll
    for (int i = 0; i < 32; i++) {
        int idx = base + i;
        if (idx < VOCAB) g_hist[idx] = run;
        run += cnt[i];
    }
}
__global__ void __launch_bounds__(256)
scatter_kernel(const int* __restrict__ ids32) {
    int is64 = sniff_is64(ids32);
    int r = blockIdx.x * 256 + threadIdx.x;
    if (r < NROWS) {
        int pos = atomicAdd(&g_hist[(int)load_id(ids32, r, is64)], 1);
        g_perm[pos] = r;
    }
}

// ---------------------------------------------------------------------------
// 5e. Embedding gather in id-sorted order: persistent grid-stride,
//     4 rows/iter, cached reads (adjacent duplicates hit L2), streaming
//     stores.
// ---------------------------------------------------------------------------
#define GATHER_BLOCKS 1184   // 148 SMs x 8 resident blocks
__global__ void __launch_bounds__(256)
gather_kernel(const int* __restrict__ ids32,
              const float* __restrict__ table,
              float* __restrict__ out) {
    __shared__ int s_is64;
    int tid = threadIdx.x;
    if (tid < 32) {
        int v = sniff_is64(ids32);
        if (tid == 0) s_is64 = v;
    }
    __syncthreads();
    int is64 = s_is64;

    for (int i0 = blockIdx.x * 4; i0 < NROWS; i0 += GATHER_BLOCKS * 4) {
        const float4* src[4];
        float4* dst[4];
        #pragma unroll
        for (int k = 0; k < 4; k++) {
            int r = g_perm[i0 + k];
            long long id = load_id(ids32, r, is64);
            src[k] = (const float4*)(table + (size_t)id * DL);
            dst[k] = (float4*)(out + (size_t)((r >> 9) * OUT_S + TOPK + (r & 511)) * DL);
        }
        float4 v[4][4];
        #pragma unroll
        for (int k = 0; k < 4; k++)
            #pragma unroll
            for (int i = 0; i < 4; i++)
                v[k][i] = src[k][tid + i * 256];
        #pragma unroll
        for (int k = 0; k < 4; k++)
            #pragma unroll
            for (int i = 0; i < 4; i++)
                __stcs(dst[k] + tid + i * 256, v[k][i]);
    }
}

// ---------------------------------------------------------------------------
// kernel_launch: fork immediately; s2 = sort chain -> gather, s3 = convertB,
// main = scores -> topk -> convA -> (wait convertB) -> cp.async mma GEMM.
// metadata order: vision_tokens, input_ids, ln_gamma, ln_beta, scorer_w,
//                 scorer_b, proj_w, proj_b, embed_table
// ---------------------------------------------------------------------------
extern "C" void kernel_launch(void* const* d_in, const int* in_sizes, int n_in,
                              void* d_out, int out_size) {
    const float* vision_tokens = (const float*)d_in[0];
    const void*  input_ids     = d_in[1];
    const float* ln_gamma      = (const float*)d_in[2];
    const float* scorer_w      = (const float*)d_in[4];
    const float* proj_w        = (const float*)d_in[6];
    const float* proj_b        = (const float*)d_in[7];
    const float* embed_table   = (const float*)d_in[8];
    float* out = (float*)d_out;

    static cudaStream_t s2 = nullptr, s3 = nullptr;
    static cudaEvent_t eFork = nullptr, eB = nullptr, eG = nullptr;
    if (s2 == nullptr) {
        cudaStreamCreateWithFlags(&s2, cudaStreamNonBlocking);
        cudaStreamCreateWithFlags(&s3, cudaStreamNonBlocking);
        cudaEventCreateWithFlags(&eFork, cudaEventDisableTiming);
        cudaEventCreateWithFlags(&eB, cudaEventDisableTiming);
        cudaEventCreateWithFlags(&eG, cudaEventDisableTiming);
        cudaFuncSetAttribute(gemm_mma_kernel,
                             cudaFuncAttributeMaxDynamicSharedMemorySize, SMEM_TOTAL);
    }

    cudaEventRecord(eFork, 0);
    cudaStreamWaitEvent(s2, eFork, 0);
    cudaStreamWaitEvent(s3, eFork, 0);

    // stream s2: counting sort by id, then the DRAM-bound gather
    const int* ids32 = (const int*)input_ids;
    hist_zero_kernel<<<(VOCAB + 255) / 256, 256, 0, s2>>>();
    hist_count_kernel<<<(NROWS + 255) / 256, 256, 0, s2>>>(ids32);
    hist_scan_kernel<<<1, 1024, 0, s2>>>();
    scatter_kernel<<<(NROWS + 255) / 256, 256, 0, s2>>>(ids32);
    gather_kernel<<<GATHER_BLOCKS, 256, 0, s2>>>(ids32, embed_table, out);
    cudaEventRecord(eG, s2);

    // stream s3: B conversion for the GEMM
    {
        dim3 gb(DL / 32, DV / 32);    // 128 x 24
        convertB_kernel<<<gb, 256, 0, s3>>>(proj_w);
    }
    cudaEventRecord(eB, s3);

    // main stream: scoring chain -> GEMM
    scores_kernel<<<(B_SZ * P_SZ * 32 + 255) / 256, 256>>>(vision_tokens, ln_gamma, scorer_w);
    topk_kernel<<<(B_SZ * 32 + 255) / 256, 256>>>();
    convertA_kernel<<<M_TOT, 128>>>(vision_tokens);
    cudaStreamWaitEvent(0, eB, 0);
    gemm_mma_kernel<<<(M_TOT / TM) * (DL / TN), 256, SMEM_TOTAL>>>(proj_b, out);

    cudaStreamWaitEvent(0, eG, 0);
}